// round 11
// baseline (speedup 1.0000x reference)
#include <cuda_runtime.h>
#include <cuda_bf16.h>
#include <cstdint>

// ----------------------------------------------------------------------------
// MaskedMSA: x@Wqkv+b -> (faithful reshape) -> causal MHA -> sa@Wout+b
// B=4, S=2048, E=1024, HIDDEN=1024, HEADS=16, d_head=64
// HMMA everywhere; GEMMs use fused 3-term hi/lo bf16 (Ah·Bh + Al·Bh + Ah·Bl)
// with single staging of all 4 tiles per k-step + XOR-swizzled SMEM.
// ----------------------------------------------------------------------------

#define B_  4
#define S_  2048
#define E_  1024
#define H3  3072
#define NH  16
#define CH  192
#define MROWS (B_ * S_)   // 8192

typedef unsigned long long ull;

// ---------------- scratch (no cudaMalloc allowed) ----------------
__device__ __nv_bfloat16 g_qkvh[MROWS * H3];
__device__ __nv_bfloat16 g_qkvl[MROWS * H3];
__device__ __nv_bfloat16 g_xh[MROWS * E_];
__device__ __nv_bfloat16 g_xl[MROWS * E_];
__device__ __nv_bfloat16 g_wqh[H3 * E_];
__device__ __nv_bfloat16 g_wql[H3 * E_];
__device__ __nv_bfloat16 g_woh[E_ * E_];
__device__ __nv_bfloat16 g_wol[E_ * E_];
__device__ __nv_bfloat16 g_sah[MROWS * E_];
__device__ __nv_bfloat16 g_sal[MROWS * E_];

// ---------------- helpers ----------------
__device__ __forceinline__ uint32_t s2u(const void* p) {
    uint32_t a;
    asm("{ .reg .u64 t; cvta.to.shared.u64 t, %1; cvt.u32.u64 %0, t; }" : "=r"(a) : "l"(p));
    return a;
}
__device__ __forceinline__ void ldm_x4(uint32_t* r, uint32_t addr) {
    asm volatile("ldmatrix.sync.aligned.m8n8.x4.shared.b16 {%0,%1,%2,%3}, [%4];"
                 : "=r"(r[0]), "=r"(r[1]), "=r"(r[2]), "=r"(r[3]) : "r"(addr));
}
__device__ __forceinline__ void ldm_x4_t(uint32_t* r, uint32_t addr) {
    asm volatile("ldmatrix.sync.aligned.m8n8.x4.trans.shared.b16 {%0,%1,%2,%3}, [%4];"
                 : "=r"(r[0]), "=r"(r[1]), "=r"(r[2]), "=r"(r[3]) : "r"(addr));
}
__device__ __forceinline__ void mma_bf16(float* d, const uint32_t* a, const uint32_t* b) {
    asm volatile("mma.sync.aligned.m16n8k16.row.col.f32.bf16.bf16.f32 "
                 "{%0,%1,%2,%3}, {%4,%5,%6,%7}, {%8,%9}, {%0,%1,%2,%3};"
                 : "+f"(d[0]), "+f"(d[1]), "+f"(d[2]), "+f"(d[3])
                 : "r"(a[0]), "r"(a[1]), "r"(a[2]), "r"(a[3]), "r"(b[0]), "r"(b[1]));
}
__device__ __forceinline__ uint32_t packbf(float lo, float hi) {
    uint32_t r; asm("cvt.rn.bf16x2.f32 %0, %1, %2;" : "=r"(r) : "f"(hi), "f"(lo)); return r;
}
__device__ __forceinline__ void cp16(uint32_t dst, const void* src) {
    asm volatile("cp.async.ca.shared.global [%0], [%1], 16;" :: "r"(dst), "l"(src));
}
__device__ __forceinline__ void cp_commit() { asm volatile("cp.async.commit_group;" ::: "memory"); }
template <int N> __device__ __forceinline__ void cp_wait() {
    asm volatile("cp.async.wait_group %0;" :: "n"(N) : "memory");
}

// ----------------------------------------------------------------------------
// Conversion kernels
// ----------------------------------------------------------------------------
__global__ void split_kernel(const float* __restrict__ in,
                             __nv_bfloat16* __restrict__ hi,
                             __nv_bfloat16* __restrict__ lo, int n4) {
    int i = blockIdx.x * blockDim.x + threadIdx.x;
    if (i >= n4) return;
    float4 v = ((const float4*)in)[i];
    uint32_t h0 = packbf(v.x, v.y), h1 = packbf(v.z, v.w);
    float f0 = __uint_as_float(h0 << 16), f1 = __uint_as_float(h0 & 0xffff0000u);
    float f2 = __uint_as_float(h1 << 16), f3 = __uint_as_float(h1 & 0xffff0000u);
    uint32_t l0 = packbf(v.x - f0, v.y - f1), l1 = packbf(v.z - f2, v.w - f3);
    ((uint32_t*)hi)[2 * i] = h0; ((uint32_t*)hi)[2 * i + 1] = h1;
    ((uint32_t*)lo)[2 * i] = l0; ((uint32_t*)lo)[2 * i + 1] = l1;
}

__global__ void transpose_split_kernel(const float* __restrict__ W,
                                       __nv_bfloat16* __restrict__ Th,
                                       __nv_bfloat16* __restrict__ Tl,
                                       int K, int N) {
    __shared__ float tile[32][33];
    const int bx = blockIdx.x * 32, by = blockIdx.y * 32;
    const int tx = threadIdx.x, ty = threadIdx.y;
#pragma unroll
    for (int i = 0; i < 32; i += 8)
        tile[ty + i][tx] = W[(by + ty + i) * N + bx + tx];
    __syncthreads();
#pragma unroll
    for (int i = 0; i < 32; i += 8) {
        float v = tile[tx][ty + i];
        __nv_bfloat16 h = __float2bfloat16(v);
        int idx = (bx + ty + i) * K + by + tx;
        Th[idx] = h;
        Tl[idx] = __float2bfloat16(v - __bfloat162float(h));
    }
}

// ----------------------------------------------------------------------------
// Fused HMMA GEMM: C = Ah@Bh^T + Al@Bh^T + Ah@Bl^T + bias
// A*: [M,K] bf16 row-major.  B*: [N,K] bf16 row-major.  Output fp32 or hi/lo.
// 128x128x32 tile, 256 threads, XOR-swizzled unpadded SMEM, cp.async 2-buffer.
// SMEM layout per buffer: [Ah | Al | Bh | Bl], each 128x32 bf16 (8 KB).
// Swizzle: element (row, quad) stored at quad' = quad ^ ((row>>1)&3), 64B rows.
// ----------------------------------------------------------------------------
#define GBM 128
#define GBN 128
#define GBK 32
#define MATB 8192
#define BUFB (4 * MATB)
#define GSMEM (2 * BUFB)    // 64 KB

__global__ __launch_bounds__(256)
void gemm_tc_kernel(const __nv_bfloat16* __restrict__ Ah, const __nv_bfloat16* __restrict__ Al,
                    const __nv_bfloat16* __restrict__ Bh, const __nv_bfloat16* __restrict__ Bl,
                    const float* __restrict__ bias, float* __restrict__ C,
                    __nv_bfloat16* __restrict__ Ch, __nv_bfloat16* __restrict__ Cl,
                    int M, int N, int K)
{
    extern __shared__ __align__(16) char gsm[];
    const uint32_t sb = s2u(gsm);
    const int t = threadIdx.x, lane = t & 31, warp = t >> 5;
    const int wm = warp & 1, wn = warp >> 1;
    const int bm = blockIdx.y * GBM, bn = blockIdx.x * GBN;

    // staging map: slot = t (+256): row = slot>>2 (invariant f), quad = slot&3
    const int srow = t >> 2;
    const int squad = t & 3;
    const uint32_t sq = (uint32_t)(squad ^ ((srow >> 1) & 3));
    const __nv_bfloat16* gsrc[4] = {
        Ah + (ull)(bm + srow) * K + squad * 8,
        Al + (ull)(bm + srow) * K + squad * 8,
        Bh + (ull)(bn + srow) * K + squad * 8,
        Bl + (ull)(bn + srow) * K + squad * 8 };
    const uint32_t sdst = sb + (uint32_t)srow * 64 + sq * 16;

    auto stage = [&](int kt, int buf) {
        const uint32_t d0 = sdst + (uint32_t)buf * BUFB;
        const int ke = kt * GBK;
#pragma unroll
        for (int m = 0; m < 4; m++) {
            cp16(d0 + m * MATB,            gsrc[m] + ke);
            cp16(d0 + m * MATB + 64 * 64,  gsrc[m] + ke + (ull)64 * K);
        }
    };

    // fragment addressing (swizzled)
    const int rA = wm * 64 + (lane & 15);
    const uint32_t fA = (uint32_t)((rA >> 1) & 3);
    const int hA = lane >> 4;
    const int rB = wn * 32 + (lane & 7) + (lane >> 4) * 8;
    const uint32_t fB = (uint32_t)((rB >> 1) & 3);
    const int hB = (lane >> 3) & 1;

    float acc[4][4][4];
#pragma unroll
    for (int mi = 0; mi < 4; mi++)
#pragma unroll
        for (int ni = 0; ni < 4; ni++)
#pragma unroll
            for (int j = 0; j < 4; j++) acc[mi][ni][j] = 0.0f;

    stage(0, 0); cp_commit();
    const int nkt = K / GBK;

    for (int kt = 0; kt < nkt; kt++) {
        const int cur = kt & 1;
        if (kt + 1 < nkt) { stage(kt + 1, cur ^ 1); cp_commit(); cp_wait<1>(); }
        else cp_wait<0>();
        __syncthreads();

        const uint32_t bb = sb + (uint32_t)cur * BUFB;
#pragma unroll
        for (int ks = 0; ks < 2; ks++) {
            uint32_t ah[4][4], al[4][4], bh[2][4], bl[2][4];
            const uint32_t qa = (((uint32_t)(2 * ks + hA)) ^ fA) * 16;
            const uint32_t qb = (((uint32_t)(2 * ks + hB)) ^ fB) * 16;
            const uint32_t arow = bb + (uint32_t)rA * 64 + qa;
            const uint32_t brow = bb + 2 * MATB + (uint32_t)rB * 64 + qb;
#pragma unroll
            for (int mi = 0; mi < 4; mi++) {
                ldm_x4(ah[mi], arow + mi * 1024);
                ldm_x4(al[mi], arow + MATB + mi * 1024);
            }
#pragma unroll
            for (int np = 0; np < 2; np++) {
                ldm_x4(bh[np], brow + np * 1024);
                ldm_x4(bl[np], brow + MATB + np * 1024);
            }
            // sweep 1: Ah x Bh
#pragma unroll
            for (int mi = 0; mi < 4; mi++)
#pragma unroll
                for (int ni = 0; ni < 4; ni++)
                    mma_bf16(acc[mi][ni], ah[mi], &bh[ni >> 1][(ni & 1) * 2]);
            // sweep 2: Al x Bh
#pragma unroll
            for (int mi = 0; mi < 4; mi++)
#pragma unroll
                for (int ni = 0; ni < 4; ni++)
                    mma_bf16(acc[mi][ni], al[mi], &bh[ni >> 1][(ni & 1) * 2]);
            // sweep 3: Ah x Bl
#pragma unroll
            for (int mi = 0; mi < 4; mi++)
#pragma unroll
                for (int ni = 0; ni < 4; ni++)
                    mma_bf16(acc[mi][ni], ah[mi], &bl[ni >> 1][(ni & 1) * 2]);
        }
        __syncthreads();
    }

    // epilogue
    const int rbase = bm + wm * 64 + (lane >> 2);
    const int cbase = bn + wn * 32 + (lane & 3) * 2;
#pragma unroll
    for (int mi = 0; mi < 4; mi++) {
#pragma unroll
        for (int ni = 0; ni < 4; ni++) {
            const int col = cbase + ni * 8;
            const float bz0 = bias[col], bz1 = bias[col + 1];
            const int r0 = rbase + mi * 16;
            float o00 = acc[mi][ni][0] + bz0, o01 = acc[mi][ni][1] + bz1;
            float o10 = acc[mi][ni][2] + bz0, o11 = acc[mi][ni][3] + bz1;
            if (Ch) {
                uint32_t h0 = packbf(o00, o01);
                uint32_t h1 = packbf(o10, o11);
                float f00 = __uint_as_float(h0 << 16), f01 = __uint_as_float(h0 & 0xffff0000u);
                float f10 = __uint_as_float(h1 << 16), f11 = __uint_as_float(h1 & 0xffff0000u);
                uint32_t l0 = packbf(o00 - f00, o01 - f01);
                uint32_t l1 = packbf(o10 - f10, o11 - f11);
                *(uint32_t*)(Ch + (ull)r0 * N + col) = h0;
                *(uint32_t*)(Ch + (ull)(r0 + 8) * N + col) = h1;
                *(uint32_t*)(Cl + (ull)r0 * N + col) = l0;
                *(uint32_t*)(Cl + (ull)(r0 + 8) * N + col) = l1;
            } else {
                float2 a0; a0.x = o00; a0.y = o01;
                float2 a1; a1.x = o10; a1.y = o11;
                *(float2*)(C + (ull)r0 * N + col) = a0;
                *(float2*)(C + (ull)(r0 + 8) * N + col) = a1;
            }
        }
    }
}

// ----------------------------------------------------------------------------
// HMMA causal flash attention (unchanged from R8 — passing at ~280us).
// ----------------------------------------------------------------------------
#define LQ 72
#define QS_ELEMS (128 * LQ)
#define MAT_ELEMS (64 * LQ)
#define ATTN_SMEM ((QS_ELEMS + 2 * 4 * MAT_ELEMS) * 2)

__device__ __forceinline__ void ldm_x2(uint32_t* r, uint32_t addr) {
    asm volatile("ldmatrix.sync.aligned.m8n8.x2.shared.b16 {%0,%1}, [%2];"
                 : "=r"(r[0]), "=r"(r[1]) : "r"(addr));
}

__global__ __launch_bounds__(256)
void attn_kernel()
{
    extern __shared__ __align__(16) __nv_bfloat16 sm[];
    __nv_bfloat16* Qs = sm;
    __nv_bfloat16* KV = sm + QS_ELEMS;

    const int t = threadIdx.x, lane = t & 31, w = t >> 5;
    const int qi = 15 - (int)blockIdx.x;
    const int bh = blockIdx.y, b = bh >> 4, h = bh & 15;
    const ull base = (ull)b * (S_ * H3) + (ull)h * (S_ * CH);
    const __nv_bfloat16* GH = g_qkvh + base;
    const __nv_bfloat16* GL = g_qkvl + base;
    const int qbase = qi * 128;

#pragma unroll
    for (int i = t; i < 128 * 8; i += 256) {
        int row = i >> 3, seg = i & 7;
        *(uint4*)(Qs + row * LQ + seg * 8) =
            *(const uint4*)(GH + (ull)(qbase + row) * CH + seg * 8);
    }

    const uint32_t kvB = s2u(KV);
    auto stage = [&](int kt, int buf) {
        const int j0 = kt * 64;
        const uint32_t dstb = kvB + buf * (4 * MAT_ELEMS * 2);
#pragma unroll
        for (int i = t; i < 4 * 64 * 8; i += 256) {
            int mmat = i >> 9;
            int row = (i >> 3) & 63;
            int seg = i & 7;
            const __nv_bfloat16* src = ((mmat & 1) ? GL : GH)
                + (ull)(j0 + row) * CH + ((mmat >= 2) ? 128 : 64) + seg * 8;
            cp16(dstb + (mmat * MAT_ELEMS + row * LQ + seg * 8) * 2, src);
        }
    };

    stage(0, 0); cp_commit();

    const int nkt = 2 * (qi + 1);
    const int r0g = qbase + w * 16 + (lane >> 2);
    const int r1g = r0g + 8;
    const float scale = 0.02209708691f;

    float m0 = -1e30f, m1 = -1e30f, l0 = 0.0f, l1 = 0.0f;
    float co[8][4];
#pragma unroll
    for (int i = 0; i < 8; i++)
#pragma unroll
        for (int j = 0; j < 4; j++) co[i][j] = 0.0f;

    uint32_t qf[4][4];
    bool qloaded = false;
    const uint32_t qaddr0 = s2u(Qs) + ((uint32_t)(w * 16 + (lane & 15)) * LQ + (lane >> 4) * 8) * 2;

    for (int kt = 0; kt < nkt; kt++) {
        const int cur = kt & 1;
        if (kt + 1 < nkt) { stage(kt + 1, cur ^ 1); cp_commit(); cp_wait<1>(); }
        else cp_wait<0>();
        __syncthreads();

        if (!qloaded) {
#pragma unroll
            for (int ks = 0; ks < 4; ks++) ldm_x4(qf[ks], qaddr0 + ks * 32);
            qloaded = true;
        }

        const uint32_t bufb = kvB + cur * (4 * MAT_ELEMS * 2);
        const uint32_t KhB = bufb, KlB = bufb + MAT_ELEMS * 2;
        const uint32_t VhB = bufb + 2 * MAT_ELEMS * 2, VlB = bufb + 3 * MAT_ELEMS * 2;

        float cs[8][4];
#pragma unroll
        for (int i = 0; i < 8; i++)
#pragma unroll
            for (int j = 0; j < 4; j++) cs[i][j] = 0.0f;

        const uint32_t kfoff = ((uint32_t)((lane & 7) + ((lane >> 4) & 1) * 8) * LQ
                                + ((lane >> 3) & 1) * 8) * 2;
#pragma unroll
        for (int pass = 0; pass < 2; pass++) {
            const uint32_t Kb = (pass ? KlB : KhB) + kfoff;
#pragma unroll
            for (int ks = 0; ks < 4; ks++) {
#pragma unroll
                for (int nip = 0; nip < 4; nip++) {
                    uint32_t bfr[4];
                    ldm_x4(bfr, Kb + ((uint32_t)nip * 16 * LQ + ks * 16) * 2);
                    mma_bf16(cs[2 * nip],     qf[ks], bfr);
                    mma_bf16(cs[2 * nip + 1], qf[ks], bfr + 2);
                }
            }
        }

        const int cb = kt * 64 + 2 * (lane & 3);
        float sv0[16], sv1[16];
        float tm0 = -1e30f, tm1 = -1e30f;
#pragma unroll
        for (int ni = 0; ni < 8; ni++) {
#pragma unroll
            for (int e = 0; e < 2; e++) {
                const int col = cb + ni * 8 + e;
                float v0 = (col <= r0g) ? cs[ni][e]     * scale : -1e30f;
                float v1 = (col <= r1g) ? cs[ni][2 + e] * scale : -1e30f;
                sv0[ni * 2 + e] = v0; sv1[ni * 2 + e] = v1;
                tm0 = fmaxf(tm0, v0); tm1 = fmaxf(tm1, v1);
            }
        }
        tm0 = fmaxf(tm0, __shfl_xor_sync(0xffffffffu, tm0, 1));
        tm0 = fmaxf(tm0, __shfl_xor_sync(0xffffffffu, tm0, 2));
        tm1 = fmaxf(tm1, __shfl_xor_sync(0xffffffffu, tm1, 1));
        tm1 = fmaxf(tm1, __shfl_xor_sync(0xffffffffu, tm1, 2));
        const float mn0 = fmaxf(m0, tm0), mn1 = fmaxf(m1, tm1);
        const float corr0 = __expf(m0 - mn0), corr1 = __expf(m1 - mn1);
        m0 = mn0; m1 = mn1;
        float ps0 = 0.0f, ps1 = 0.0f;
#pragma unroll
        for (int i = 0; i < 16; i++) {
            sv0[i] = __expf(sv0[i] - mn0); ps0 += sv0[i];
            sv1[i] = __expf(sv1[i] - mn1); ps1 += sv1[i];
        }
        ps0 += __shfl_xor_sync(0xffffffffu, ps0, 1);
        ps0 += __shfl_xor_sync(0xffffffffu, ps0, 2);
        ps1 += __shfl_xor_sync(0xffffffffu, ps1, 1);
        ps1 += __shfl_xor_sync(0xffffffffu, ps1, 2);
        l0 = l0 * corr0 + ps0;
        l1 = l1 * corr1 + ps1;
#pragma unroll
        for (int nd = 0; nd < 8; nd++) {
            co[nd][0] *= corr0; co[nd][1] *= corr0;
            co[nd][2] *= corr1; co[nd][3] *= corr1;
        }

        uint32_t ph[4][4], pl[4][4];
#pragma unroll
        for (int kj = 0; kj < 4; kj++) {
            uint32_t a0 = packbf(sv0[4 * kj],     sv0[4 * kj + 1]);
            uint32_t a1 = packbf(sv1[4 * kj],     sv1[4 * kj + 1]);
            uint32_t a2 = packbf(sv0[4 * kj + 2], sv0[4 * kj + 3]);
            uint32_t a3 = packbf(sv1[4 * kj + 2], sv1[4 * kj + 3]);
            ph[kj][0] = a0; ph[kj][1] = a1; ph[kj][2] = a2; ph[kj][3] = a3;
            pl[kj][0] = packbf(sv0[4 * kj]     - __uint_as_float(a0 << 16),
                               sv0[4 * kj + 1] - __uint_as_float(a0 & 0xffff0000u));
            pl[kj][1] = packbf(sv1[4 * kj]     - __uint_as_float(a1 << 16),
                               sv1[4 * kj + 1] - __uint_as_float(a1 & 0xffff0000u));
            pl[kj][2] = packbf(sv0[4 * kj + 2] - __uint_as_float(a2 << 16),
                               sv0[4 * kj + 3] - __uint_as_float(a2 & 0xffff0000u));
            pl[kj][3] = packbf(sv1[4 * kj + 2] - __uint_as_float(a3 << 16),
                               sv1[4 * kj + 3] - __uint_as_float(a3 & 0xffff0000u));
        }

        const uint32_t vfoff = ((uint32_t)(lane & 15) * LQ) * 2 + (lane >> 4) * 16;
#pragma unroll
        for (int pass = 0; pass < 3; pass++) {
            const uint32_t Vb = ((pass == 1) ? VlB : VhB) + vfoff;
            const uint32_t (*pa)[4] = (pass == 2) ? pl : ph;
#pragma unroll
            for (int kj = 0; kj < 4; kj++) {
#pragma unroll
                for (int ndp = 0; ndp < 4; ndp++) {
                    uint32_t bfr[4];
                    ldm_x4_t(bfr, Vb + (uint32_t)kj * 16 * LQ * 2 + ndp * 32);
                    mma_bf16(co[2 * ndp],     pa[kj], bfr);
                    mma_bf16(co[2 * ndp + 1], pa[kj], bfr + 2);
                }
            }
        }
        __syncthreads();
    }

    const float il0 = 1.0f / l0, il1 = 1.0f / l1;
    const ull row0 = (ull)(b * S_ + h * 128 + (r0g >> 4)) * E_ + (r0g & 15) * 64;
    const ull row1 = (ull)(b * S_ + h * 128 + (r1g >> 4)) * E_ + (r1g & 15) * 64;
    const int dcol = 2 * (lane & 3);
#pragma unroll
    for (int nd = 0; nd < 8; nd++) {
        const int d = nd * 8 + dcol;
        float o00 = co[nd][0] * il0, o01 = co[nd][1] * il0;
        float o10 = co[nd][2] * il1, o11 = co[nd][3] * il1;
        uint32_t h0 = packbf(o00, o01);
        uint32_t h1 = packbf(o10, o11);
        uint32_t q0 = packbf(o00 - __uint_as_float(h0 << 16),
                             o01 - __uint_as_float(h0 & 0xffff0000u));
        uint32_t q1 = packbf(o10 - __uint_as_float(h1 << 16),
                             o11 - __uint_as_float(h1 & 0xffff0000u));
        *(uint32_t*)(g_sah + row0 + d) = h0;
        *(uint32_t*)(g_sah + row1 + d) = h1;
        *(uint32_t*)(g_sal + row0 + d) = q0;
        *(uint32_t*)(g_sal + row1 + d) = q1;
    }
}

// ----------------------------------------------------------------------------
extern "C" void kernel_launch(void* const* d_in, const int* in_sizes, int n_in,
                              void* d_out, int out_size)
{
    const float* x     = (const float*)d_in[0];
    const float* W_qkv = (const float*)d_in[1];
    const float* b_qkv = (const float*)d_in[2];
    const float* W_out = (const float*)d_in[3];
    const float* b_out = (const float*)d_in[4];
    float* out = (float*)d_out;

    __nv_bfloat16 *qh, *ql, *xh, *xl, *wqh, *wql, *woh, *wol, *sah, *sal;
    cudaGetSymbolAddress((void**)&qh, g_qkvh); cudaGetSymbolAddress((void**)&ql, g_qkvl);
    cudaGetSymbolAddress((void**)&xh, g_xh);   cudaGetSymbolAddress((void**)&xl, g_xl);
    cudaGetSymbolAddress((void**)&wqh, g_wqh); cudaGetSymbolAddress((void**)&wql, g_wql);
    cudaGetSymbolAddress((void**)&woh, g_woh); cudaGetSymbolAddress((void**)&wol, g_wol);
    cudaGetSymbolAddress((void**)&sah, g_sah); cudaGetSymbolAddress((void**)&sal, g_sal);

    cudaFuncSetAttribute(attn_kernel,
                         cudaFuncAttributeMaxDynamicSharedMemorySize, ATTN_SMEM);
    cudaFuncSetAttribute(gemm_tc_kernel,
                         cudaFuncAttributeMaxDynamicSharedMemorySize, GSMEM);

    // 0) operand prep
    {
        const int n4 = MROWS * E_ / 4;
        split_kernel<<<(n4 + 255) / 256, 256>>>(x, xh, xl, n4);
        transpose_split_kernel<<<dim3(H3 / 32, E_ / 32), dim3(32, 8)>>>(
            W_qkv, wqh, wql, E_, H3);
        transpose_split_kernel<<<dim3(E_ / 32, E_ / 32), dim3(32, 8)>>>(
            W_out, woh, wol, E_, E_);
    }

    // 1) QKV projection -> hi/lo bf16 qkv
    gemm_tc_kernel<<<dim3(H3 / GBN, MROWS / GBM), 256, GSMEM>>>(
        xh, xl, wqh, wql, b_qkv, nullptr, qh, ql, MROWS, H3, E_);

    // 2) HMMA causal attention -> hi/lo bf16 sa
    attn_kernel<<<dim3(16, B_ * NH), 256, ATTN_SMEM>>>();

    // 3) output projection -> fp32 out
    gemm_tc_kernel<<<dim3(E_ / GBN, MROWS / GBM), 256, GSMEM>>>(
        sah, sal, woh, wol, b_out, out, nullptr, nullptr, MROWS, E_, E_);
}

// round 12
// speedup vs baseline: 1.0716x; 1.0716x over previous
#include <cuda_runtime.h>
#include <cuda_bf16.h>
#include <cstdint>

// ----------------------------------------------------------------------------
// MaskedMSA: x@Wqkv+b -> (faithful reshape) -> causal MHA -> sa@Wout+b
// B=4, S=2048, E=1024, HIDDEN=1024, HEADS=16, d_head=64
// HMMA everywhere; fused 3-term hi/lo bf16 GEMM (Ah·Bh + Al·Bh + Ah·Bl),
// XOR-swizzled SMEM, cp.async double buffer, <=128 regs -> 2 CTAs/SM.
// ----------------------------------------------------------------------------

#define B_  4
#define S_  2048
#define E_  1024
#define H3  3072
#define NH  16
#define CH  192
#define MROWS (B_ * S_)   // 8192

typedef unsigned long long ull;

// ---------------- scratch (no cudaMalloc allowed) ----------------
__device__ __nv_bfloat16 g_qkvh[MROWS * H3];
__device__ __nv_bfloat16 g_qkvl[MROWS * H3];
__device__ __nv_bfloat16 g_xh[MROWS * E_];
__device__ __nv_bfloat16 g_xl[MROWS * E_];
__device__ __nv_bfloat16 g_wqh[H3 * E_];
__device__ __nv_bfloat16 g_wql[H3 * E_];
__device__ __nv_bfloat16 g_woh[E_ * E_];
__device__ __nv_bfloat16 g_wol[E_ * E_];
__device__ __nv_bfloat16 g_sah[MROWS * E_];
__device__ __nv_bfloat16 g_sal[MROWS * E_];

// ---------------- helpers ----------------
__device__ __forceinline__ uint32_t s2u(const void* p) {
    uint32_t a;
    asm("{ .reg .u64 t; cvta.to.shared.u64 t, %1; cvt.u32.u64 %0, t; }" : "=r"(a) : "l"(p));
    return a;
}
__device__ __forceinline__ void ldm_x4(uint32_t* r, uint32_t addr) {
    asm volatile("ldmatrix.sync.aligned.m8n8.x4.shared.b16 {%0,%1,%2,%3}, [%4];"
                 : "=r"(r[0]), "=r"(r[1]), "=r"(r[2]), "=r"(r[3]) : "r"(addr));
}
__device__ __forceinline__ void ldm_x4_t(uint32_t* r, uint32_t addr) {
    asm volatile("ldmatrix.sync.aligned.m8n8.x4.trans.shared.b16 {%0,%1,%2,%3}, [%4];"
                 : "=r"(r[0]), "=r"(r[1]), "=r"(r[2]), "=r"(r[3]) : "r"(addr));
}
__device__ __forceinline__ void mma_bf16(float* d, const uint32_t* a, const uint32_t* b) {
    asm volatile("mma.sync.aligned.m16n8k16.row.col.f32.bf16.bf16.f32 "
                 "{%0,%1,%2,%3}, {%4,%5,%6,%7}, {%8,%9}, {%0,%1,%2,%3};"
                 : "+f"(d[0]), "+f"(d[1]), "+f"(d[2]), "+f"(d[3])
                 : "r"(a[0]), "r"(a[1]), "r"(a[2]), "r"(a[3]), "r"(b[0]), "r"(b[1]));
}
__device__ __forceinline__ uint32_t packbf(float lo, float hi) {
    uint32_t r; asm("cvt.rn.bf16x2.f32 %0, %1, %2;" : "=r"(r) : "f"(hi), "f"(lo)); return r;
}
__device__ __forceinline__ void cp16(uint32_t dst, const void* src) {
    asm volatile("cp.async.ca.shared.global [%0], [%1], 16;" :: "r"(dst), "l"(src));
}
__device__ __forceinline__ void cp_commit() { asm volatile("cp.async.commit_group;" ::: "memory"); }
template <int N> __device__ __forceinline__ void cp_wait() {
    asm volatile("cp.async.wait_group %0;" :: "n"(N) : "memory");
}

// ----------------------------------------------------------------------------
// Conversion kernels
// ----------------------------------------------------------------------------
__global__ void split_kernel(const float* __restrict__ in,
                             __nv_bfloat16* __restrict__ hi,
                             __nv_bfloat16* __restrict__ lo, int n4) {
    int i = blockIdx.x * blockDim.x + threadIdx.x;
    if (i >= n4) return;
    float4 v = ((const float4*)in)[i];
    uint32_t h0 = packbf(v.x, v.y), h1 = packbf(v.z, v.w);
    float f0 = __uint_as_float(h0 << 16), f1 = __uint_as_float(h0 & 0xffff0000u);
    float f2 = __uint_as_float(h1 << 16), f3 = __uint_as_float(h1 & 0xffff0000u);
    uint32_t l0 = packbf(v.x - f0, v.y - f1), l1 = packbf(v.z - f2, v.w - f3);
    ((uint32_t*)hi)[2 * i] = h0; ((uint32_t*)hi)[2 * i + 1] = h1;
    ((uint32_t*)lo)[2 * i] = l0; ((uint32_t*)lo)[2 * i + 1] = l1;
}

__global__ void transpose_split_kernel(const float* __restrict__ W,
                                       __nv_bfloat16* __restrict__ Th,
                                       __nv_bfloat16* __restrict__ Tl,
                                       int K, int N) {
    __shared__ float tile[32][33];
    const int bx = blockIdx.x * 32, by = blockIdx.y * 32;
    const int tx = threadIdx.x, ty = threadIdx.y;
#pragma unroll
    for (int i = 0; i < 32; i += 8)
        tile[ty + i][tx] = W[(by + ty + i) * N + bx + tx];
    __syncthreads();
#pragma unroll
    for (int i = 0; i < 32; i += 8) {
        float v = tile[tx][ty + i];
        __nv_bfloat16 h = __float2bfloat16(v);
        int idx = (bx + ty + i) * K + by + tx;
        Th[idx] = h;
        Tl[idx] = __float2bfloat16(v - __bfloat162float(h));
    }
}

// ----------------------------------------------------------------------------
// Fused HMMA GEMM: C = Ah@Bh^T + Al@Bh^T + Ah@Bl^T + bias
// 128x128x32 tile, 256 threads, XOR-swizzled SMEM, cp.async 2-buffer.
// Register-trimmed (<=128) for 2 CTAs/SM.
// ----------------------------------------------------------------------------
#define GBM 128
#define GBN 128
#define GBK 32
#define MATB 8192
#define BUFB (4 * MATB)
#define GSMEM (2 * BUFB)    // 64 KB

__global__ __launch_bounds__(256, 2)
void gemm_tc_kernel(const __nv_bfloat16* __restrict__ Ah, const __nv_bfloat16* __restrict__ Al,
                    const __nv_bfloat16* __restrict__ Bh, const __nv_bfloat16* __restrict__ Bl,
                    const float* __restrict__ bias, float* __restrict__ C,
                    __nv_bfloat16* __restrict__ Ch, __nv_bfloat16* __restrict__ Cl,
                    int M, int N, int K)
{
    extern __shared__ __align__(16) char gsm[];
    const uint32_t sb = s2u(gsm);
    const int t = threadIdx.x, lane = t & 31, warp = t >> 5;
    const int wm = warp & 1, wn = warp >> 1;
    const int bm = blockIdx.y * GBM, bn = blockIdx.x * GBN;

    // staging map: row = t>>2, quad = t&3; base pointers + lo-deltas (reg diet)
    const int srow = t >> 2;
    const int squad = t & 3;
    const uint32_t sq = (uint32_t)(squad ^ ((srow >> 1) & 3));
    const __nv_bfloat16* a0 = Ah + (ull)(bm + srow) * K + squad * 8;
    const __nv_bfloat16* b0 = Bh + (ull)(bn + srow) * K + squad * 8;
    const long dal = (long)(Al - Ah);
    const long dbl = (long)(Bl - Bh);
    const uint32_t sdst = sb + (uint32_t)srow * 64 + sq * 16;

    auto stage = [&](int kt, int buf) {
        const uint32_t d0 = sdst + (uint32_t)buf * BUFB;
        const __nv_bfloat16* ap = a0 + kt * GBK;
        const __nv_bfloat16* bp = b0 + kt * GBK;
        cp16(d0,                       ap);
        cp16(d0 + 64 * 64,             ap + (ull)64 * K);
        cp16(d0 + MATB,                ap + dal);
        cp16(d0 + MATB + 64 * 64,      ap + dal + (ull)64 * K);
        cp16(d0 + 2 * MATB,            bp);
        cp16(d0 + 2 * MATB + 64 * 64,  bp + (ull)64 * K);
        cp16(d0 + 3 * MATB,            bp + dbl);
        cp16(d0 + 3 * MATB + 64 * 64,  bp + dbl + (ull)64 * K);
    };

    // fragment addressing (swizzled)
    const int rA = wm * 64 + (lane & 15);
    const uint32_t fA = (uint32_t)((rA >> 1) & 3);
    const int hA = lane >> 4;
    const int rB = wn * 32 + (lane & 7) + (lane >> 4) * 8;
    const uint32_t fB = (uint32_t)((rB >> 1) & 3);
    const int hB = (lane >> 3) & 1;

    float acc[4][4][4];
#pragma unroll
    for (int mi = 0; mi < 4; mi++)
#pragma unroll
        for (int ni = 0; ni < 4; ni++)
#pragma unroll
            for (int j = 0; j < 4; j++) acc[mi][ni][j] = 0.0f;

    stage(0, 0); cp_commit();
    const int nkt = K / GBK;

    for (int kt = 0; kt < nkt; kt++) {
        const int cur = kt & 1;
        if (kt + 1 < nkt) { stage(kt + 1, cur ^ 1); cp_commit(); cp_wait<1>(); }
        else cp_wait<0>();
        __syncthreads();

        const uint32_t bb = sb + (uint32_t)cur * BUFB;
#pragma unroll
        for (int ks = 0; ks < 2; ks++) {
            uint32_t bh[2][4], bl[2][4];
            const uint32_t qa = (((uint32_t)(2 * ks + hA)) ^ fA) * 16;
            const uint32_t qb = (((uint32_t)(2 * ks + hB)) ^ fB) * 16;
            const uint32_t arow = bb + (uint32_t)rA * 64 + qa;
            const uint32_t brow = bb + 2 * MATB + (uint32_t)rB * 64 + qb;
#pragma unroll
            for (int np = 0; np < 2; np++) {
                ldm_x4(bh[np], brow + np * 1024);
                ldm_x4(bl[np], brow + MATB + np * 1024);
            }
            // per-mi: load A hi/lo fragments, fire the 3 sweeps (12 MMAs)
#pragma unroll
            for (int mi = 0; mi < 4; mi++) {
                uint32_t ah[4], al[4];
                ldm_x4(ah, arow + mi * 1024);
                ldm_x4(al, arow + MATB + mi * 1024);
#pragma unroll
                for (int ni = 0; ni < 4; ni++)
                    mma_bf16(acc[mi][ni], ah, &bh[ni >> 1][(ni & 1) * 2]);
#pragma unroll
                for (int ni = 0; ni < 4; ni++)
                    mma_bf16(acc[mi][ni], al, &bh[ni >> 1][(ni & 1) * 2]);
#pragma unroll
                for (int ni = 0; ni < 4; ni++)
                    mma_bf16(acc[mi][ni], ah, &bl[ni >> 1][(ni & 1) * 2]);
            }
        }
        __syncthreads();
    }

    // epilogue
    const int rbase = bm + wm * 64 + (lane >> 2);
    const int cbase = bn + wn * 32 + (lane & 3) * 2;
#pragma unroll
    for (int mi = 0; mi < 4; mi++) {
#pragma unroll
        for (int ni = 0; ni < 4; ni++) {
            const int col = cbase + ni * 8;
            const float bz0 = bias[col], bz1 = bias[col + 1];
            const int r0 = rbase + mi * 16;
            float o00 = acc[mi][ni][0] + bz0, o01 = acc[mi][ni][1] + bz1;
            float o10 = acc[mi][ni][2] + bz0, o11 = acc[mi][ni][3] + bz1;
            if (Ch) {
                uint32_t h0 = packbf(o00, o01);
                uint32_t h1 = packbf(o10, o11);
                float f00 = __uint_as_float(h0 << 16), f01 = __uint_as_float(h0 & 0xffff0000u);
                float f10 = __uint_as_float(h1 << 16), f11 = __uint_as_float(h1 & 0xffff0000u);
                uint32_t l0 = packbf(o00 - f00, o01 - f01);
                uint32_t l1 = packbf(o10 - f10, o11 - f11);
                *(uint32_t*)(Ch + (ull)r0 * N + col) = h0;
                *(uint32_t*)(Ch + (ull)(r0 + 8) * N + col) = h1;
                *(uint32_t*)(Cl + (ull)r0 * N + col) = l0;
                *(uint32_t*)(Cl + (ull)(r0 + 8) * N + col) = l1;
            } else {
                float2 ax; ax.x = o00; ax.y = o01;
                float2 ay; ay.x = o10; ay.y = o11;
                *(float2*)(C + (ull)r0 * N + col) = ax;
                *(float2*)(C + (ull)(r0 + 8) * N + col) = ay;
            }
        }
    }
}

// ----------------------------------------------------------------------------
// HMMA causal flash attention (unchanged — ~280us).
// ----------------------------------------------------------------------------
#define LQ 72
#define QS_ELEMS (128 * LQ)
#define MAT_ELEMS (64 * LQ)
#define ATTN_SMEM ((QS_ELEMS + 2 * 4 * MAT_ELEMS) * 2)

__global__ __launch_bounds__(256)
void attn_kernel()
{
    extern __shared__ __align__(16) __nv_bfloat16 sm[];
    __nv_bfloat16* Qs = sm;
    __nv_bfloat16* KV = sm + QS_ELEMS;

    const int t = threadIdx.x, lane = t & 31, w = t >> 5;
    const int qi = 15 - (int)blockIdx.x;
    const int bh = blockIdx.y, b = bh >> 4, h = bh & 15;
    const ull base = (ull)b * (S_ * H3) + (ull)h * (S_ * CH);
    const __nv_bfloat16* GH = g_qkvh + base;
    const __nv_bfloat16* GL = g_qkvl + base;
    const int qbase = qi * 128;

#pragma unroll
    for (int i = t; i < 128 * 8; i += 256) {
        int row = i >> 3, seg = i & 7;
        *(uint4*)(Qs + row * LQ + seg * 8) =
            *(const uint4*)(GH + (ull)(qbase + row) * CH + seg * 8);
    }

    const uint32_t kvB = s2u(KV);
    auto stage = [&](int kt, int buf) {
        const int j0 = kt * 64;
        const uint32_t dstb = kvB + buf * (4 * MAT_ELEMS * 2);
#pragma unroll
        for (int i = t; i < 4 * 64 * 8; i += 256) {
            int mmat = i >> 9;
            int row = (i >> 3) & 63;
            int seg = i & 7;
            const __nv_bfloat16* src = ((mmat & 1) ? GL : GH)
                + (ull)(j0 + row) * CH + ((mmat >= 2) ? 128 : 64) + seg * 8;
            cp16(dstb + (mmat * MAT_ELEMS + row * LQ + seg * 8) * 2, src);
        }
    };

    stage(0, 0); cp_commit();

    const int nkt = 2 * (qi + 1);
    const int r0g = qbase + w * 16 + (lane >> 2);
    const int r1g = r0g + 8;
    const float scale = 0.02209708691f;

    float m0 = -1e30f, m1 = -1e30f, l0 = 0.0f, l1 = 0.0f;
    float co[8][4];
#pragma unroll
    for (int i = 0; i < 8; i++)
#pragma unroll
        for (int j = 0; j < 4; j++) co[i][j] = 0.0f;

    uint32_t qf[4][4];
    bool qloaded = false;
    const uint32_t qaddr0 = s2u(Qs) + ((uint32_t)(w * 16 + (lane & 15)) * LQ + (lane >> 4) * 8) * 2;

    for (int kt = 0; kt < nkt; kt++) {
        const int cur = kt & 1;
        if (kt + 1 < nkt) { stage(kt + 1, cur ^ 1); cp_commit(); cp_wait<1>(); }
        else cp_wait<0>();
        __syncthreads();

        if (!qloaded) {
#pragma unroll
            for (int ks = 0; ks < 4; ks++) ldm_x4(qf[ks], qaddr0 + ks * 32);
            qloaded = true;
        }

        const uint32_t bufb = kvB + cur * (4 * MAT_ELEMS * 2);
        const uint32_t KhB = bufb, KlB = bufb + MAT_ELEMS * 2;
        const uint32_t VhB = bufb + 2 * MAT_ELEMS * 2, VlB = bufb + 3 * MAT_ELEMS * 2;

        float cs[8][4];
#pragma unroll
        for (int i = 0; i < 8; i++)
#pragma unroll
            for (int j = 0; j < 4; j++) cs[i][j] = 0.0f;

        const uint32_t kfoff = ((uint32_t)((lane & 7) + ((lane >> 4) & 1) * 8) * LQ
                                + ((lane >> 3) & 1) * 8) * 2;
#pragma unroll
        for (int pass = 0; pass < 2; pass++) {
            const uint32_t Kb = (pass ? KlB : KhB) + kfoff;
#pragma unroll
            for (int ks = 0; ks < 4; ks++) {
#pragma unroll
                for (int nip = 0; nip < 4; nip++) {
                    uint32_t bfr[4];
                    ldm_x4(bfr, Kb + ((uint32_t)nip * 16 * LQ + ks * 16) * 2);
                    mma_bf16(cs[2 * nip],     qf[ks], bfr);
                    mma_bf16(cs[2 * nip + 1], qf[ks], bfr + 2);
                }
            }
        }

        const int cb = kt * 64 + 2 * (lane & 3);
        float sv0[16], sv1[16];
        float tm0 = -1e30f, tm1 = -1e30f;
#pragma unroll
        for (int ni = 0; ni < 8; ni++) {
#pragma unroll
            for (int e = 0; e < 2; e++) {
                const int col = cb + ni * 8 + e;
                float v0 = (col <= r0g) ? cs[ni][e]     * scale : -1e30f;
                float v1 = (col <= r1g) ? cs[ni][2 + e] * scale : -1e30f;
                sv0[ni * 2 + e] = v0; sv1[ni * 2 + e] = v1;
                tm0 = fmaxf(tm0, v0); tm1 = fmaxf(tm1, v1);
            }
        }
        tm0 = fmaxf(tm0, __shfl_xor_sync(0xffffffffu, tm0, 1));
        tm0 = fmaxf(tm0, __shfl_xor_sync(0xffffffffu, tm0, 2));
        tm1 = fmaxf(tm1, __shfl_xor_sync(0xffffffffu, tm1, 1));
        tm1 = fmaxf(tm1, __shfl_xor_sync(0xffffffffu, tm1, 2));
        const float mn0 = fmaxf(m0, tm0), mn1 = fmaxf(m1, tm1);
        const float corr0 = __expf(m0 - mn0), corr1 = __expf(m1 - mn1);
        m0 = mn0; m1 = mn1;
        float ps0 = 0.0f, ps1 = 0.0f;
#pragma unroll
        for (int i = 0; i < 16; i++) {
            sv0[i] = __expf(sv0[i] - mn0); ps0 += sv0[i];
            sv1[i] = __expf(sv1[i] - mn1); ps1 += sv1[i];
        }
        ps0 += __shfl_xor_sync(0xffffffffu, ps0, 1);
        ps0 += __shfl_xor_sync(0xffffffffu, ps0, 2);
        ps1 += __shfl_xor_sync(0xffffffffu, ps1, 1);
        ps1 += __shfl_xor_sync(0xffffffffu, ps1, 2);
        l0 = l0 * corr0 + ps0;
        l1 = l1 * corr1 + ps1;
#pragma unroll
        for (int nd = 0; nd < 8; nd++) {
            co[nd][0] *= corr0; co[nd][1] *= corr0;
            co[nd][2] *= corr1; co[nd][3] *= corr1;
        }

        uint32_t ph[4][4], pl[4][4];
#pragma unroll
        for (int kj = 0; kj < 4; kj++) {
            uint32_t a0 = packbf(sv0[4 * kj],     sv0[4 * kj + 1]);
            uint32_t a1 = packbf(sv1[4 * kj],     sv1[4 * kj + 1]);
            uint32_t a2 = packbf(sv0[4 * kj + 2], sv0[4 * kj + 3]);
            uint32_t a3 = packbf(sv1[4 * kj + 2], sv1[4 * kj + 3]);
            ph[kj][0] = a0; ph[kj][1] = a1; ph[kj][2] = a2; ph[kj][3] = a3;
            pl[kj][0] = packbf(sv0[4 * kj]     - __uint_as_float(a0 << 16),
                               sv0[4 * kj + 1] - __uint_as_float(a0 & 0xffff0000u));
            pl[kj][1] = packbf(sv1[4 * kj]     - __uint_as_float(a1 << 16),
                               sv1[4 * kj + 1] - __uint_as_float(a1 & 0xffff0000u));
            pl[kj][2] = packbf(sv0[4 * kj + 2] - __uint_as_float(a2 << 16),
                               sv0[4 * kj + 3] - __uint_as_float(a2 & 0xffff0000u));
            pl[kj][3] = packbf(sv1[4 * kj + 2] - __uint_as_float(a3 << 16),
                               sv1[4 * kj + 3] - __uint_as_float(a3 & 0xffff0000u));
        }

        const uint32_t vfoff = ((uint32_t)(lane & 15) * LQ) * 2 + (lane >> 4) * 16;
#pragma unroll
        for (int pass = 0; pass < 3; pass++) {
            const uint32_t Vb = ((pass == 1) ? VlB : VhB) + vfoff;
            const uint32_t (*pa)[4] = (pass == 2) ? pl : ph;
#pragma unroll
            for (int kj = 0; kj < 4; kj++) {
#pragma unroll
                for (int ndp = 0; ndp < 4; ndp++) {
                    uint32_t bfr[4];
                    ldm_x4_t(bfr, Vb + (uint32_t)kj * 16 * LQ * 2 + ndp * 32);
                    mma_bf16(co[2 * ndp],     pa[kj], bfr);
                    mma_bf16(co[2 * ndp + 1], pa[kj], bfr + 2);
                }
            }
        }
        __syncthreads();
    }

    const float il0 = 1.0f / l0, il1 = 1.0f / l1;
    const ull row0 = (ull)(b * S_ + h * 128 + (r0g >> 4)) * E_ + (r0g & 15) * 64;
    const ull row1 = (ull)(b * S_ + h * 128 + (r1g >> 4)) * E_ + (r1g & 15) * 64;
    const int dcol = 2 * (lane & 3);
#pragma unroll
    for (int nd = 0; nd < 8; nd++) {
        const int d = nd * 8 + dcol;
        float o00 = co[nd][0] * il0, o01 = co[nd][1] * il0;
        float o10 = co[nd][2] * il1, o11 = co[nd][3] * il1;
        uint32_t h0 = packbf(o00, o01);
        uint32_t h1 = packbf(o10, o11);
        uint32_t q0 = packbf(o00 - __uint_as_float(h0 << 16),
                             o01 - __uint_as_float(h0 & 0xffff0000u));
        uint32_t q1 = packbf(o10 - __uint_as_float(h1 << 16),
                             o11 - __uint_as_float(h1 & 0xffff0000u));
        *(uint32_t*)(g_sah + row0 + d) = h0;
        *(uint32_t*)(g_sah + row1 + d) = h1;
        *(uint32_t*)(g_sal + row0 + d) = q0;
        *(uint32_t*)(g_sal + row1 + d) = q1;
    }
}

// ----------------------------------------------------------------------------
extern "C" void kernel_launch(void* const* d_in, const int* in_sizes, int n_in,
                              void* d_out, int out_size)
{
    const float* x     = (const float*)d_in[0];
    const float* W_qkv = (const float*)d_in[1];
    const float* b_qkv = (const float*)d_in[2];
    const float* W_out = (const float*)d_in[3];
    const float* b_out = (const float*)d_in[4];
    float* out = (float*)d_out;

    __nv_bfloat16 *qh, *ql, *xh, *xl, *wqh, *wql, *woh, *wol, *sah, *sal;
    cudaGetSymbolAddress((void**)&qh, g_qkvh); cudaGetSymbolAddress((void**)&ql, g_qkvl);
    cudaGetSymbolAddress((void**)&xh, g_xh);   cudaGetSymbolAddress((void**)&xl, g_xl);
    cudaGetSymbolAddress((void**)&wqh, g_wqh); cudaGetSymbolAddress((void**)&wql, g_wql);
    cudaGetSymbolAddress((void**)&woh, g_woh); cudaGetSymbolAddress((void**)&wol, g_wol);
    cudaGetSymbolAddress((void**)&sah, g_sah); cudaGetSymbolAddress((void**)&sal, g_sal);

    cudaFuncSetAttribute(attn_kernel,
                         cudaFuncAttributeMaxDynamicSharedMemorySize, ATTN_SMEM);
    cudaFuncSetAttribute(gemm_tc_kernel,
                         cudaFuncAttributeMaxDynamicSharedMemorySize, GSMEM);

    // 0) operand prep
    {
        const int n4 = MROWS * E_ / 4;
        split_kernel<<<(n4 + 255) / 256, 256>>>(x, xh, xl, n4);
        transpose_split_kernel<<<dim3(H3 / 32, E_ / 32), dim3(32, 8)>>>(
            W_qkv, wqh, wql, E_, H3);
        transpose_split_kernel<<<dim3(E_ / 32, E_ / 32), dim3(32, 8)>>>(
            W_out, woh, wol, E_, E_);
    }

    // 1) QKV projection -> hi/lo bf16 qkv
    gemm_tc_kernel<<<dim3(H3 / GBN, MROWS / GBM), 256, GSMEM>>>(
        xh, xl, wqh, wql, b_qkv, nullptr, qh, ql, MROWS, H3, E_);

    // 2) HMMA causal attention -> hi/lo bf16 sa
    attn_kernel<<<dim3(16, B_ * NH), 256, ATTN_SMEM>>>();

    // 3) output projection -> fp32 out
    gemm_tc_kernel<<<dim3(E_ / GBN, MROWS / GBM), 256, GSMEM>>>(
        sah, sal, woh, wol, b_out, out, nullptr, nullptr, MROWS, E_, E_);
}

// round 14
// speedup vs baseline: 1.4741x; 1.3756x over previous
#include <cuda_runtime.h>
#include <cuda_fp16.h>
#include <cstdint>

// ----------------------------------------------------------------------------
// MaskedMSA: x@Wqkv+b -> (faithful reshape) -> causal MHA -> sa@Wout+b
// B=4, S=2048, E=1024, HIDDEN=1024, HEADS=16, d_head=64
// fp16 HMMA everywhere. GEMMs: 2-pass (Ah+Al)@W_fp16. Attention: QK 1-pass,
// PV 2-pass via P hi/lo split (V fragments reused). Linear-path error ~5e-4.
// ----------------------------------------------------------------------------

#define B_  4
#define S_  2048
#define E_  1024
#define H3  3072
#define NH  16
#define CH  192
#define MROWS (B_ * S_)   // 8192

typedef unsigned long long ull;

// ---------------- scratch (no cudaMalloc allowed) ----------------
__device__ __half g_qkv[MROWS * H3];     // qkv, single fp16
__device__ __half g_xh[MROWS * E_];      // x hi/lo fp16
__device__ __half g_xl[MROWS * E_];
__device__ __half g_wq[H3 * E_];         // W_qkv^T fp16 (single)
__device__ __half g_wo[E_ * E_];         // W_out^T fp16 (single)
__device__ __half g_sah[MROWS * E_];     // attention out hi/lo fp16
__device__ __half g_sal[MROWS * E_];

// ---------------- helpers ----------------
__device__ __forceinline__ uint32_t s2u(const void* p) {
    uint32_t a;
    asm("{ .reg .u64 t; cvta.to.shared.u64 t, %1; cvt.u32.u64 %0, t; }" : "=r"(a) : "l"(p));
    return a;
}
__device__ __forceinline__ void ldm_x4(uint32_t* r, uint32_t addr) {
    asm volatile("ldmatrix.sync.aligned.m8n8.x4.shared.b16 {%0,%1,%2,%3}, [%4];"
                 : "=r"(r[0]), "=r"(r[1]), "=r"(r[2]), "=r"(r[3]) : "r"(addr));
}
__device__ __forceinline__ void ldm_x4_t(uint32_t* r, uint32_t addr) {
    asm volatile("ldmatrix.sync.aligned.m8n8.x4.trans.shared.b16 {%0,%1,%2,%3}, [%4];"
                 : "=r"(r[0]), "=r"(r[1]), "=r"(r[2]), "=r"(r[3]) : "r"(addr));
}
__device__ __forceinline__ void mma16(float* d, const uint32_t* a, const uint32_t* b) {
    asm volatile("mma.sync.aligned.m16n8k16.row.col.f32.f16.f16.f32 "
                 "{%0,%1,%2,%3}, {%4,%5,%6,%7}, {%8,%9}, {%0,%1,%2,%3};"
                 : "+f"(d[0]), "+f"(d[1]), "+f"(d[2]), "+f"(d[3])
                 : "r"(a[0]), "r"(a[1]), "r"(a[2]), "r"(a[3]), "r"(b[0]), "r"(b[1]));
}
// pack (lo, hi) floats into f16x2 (lo in bits[15:0])
__device__ __forceinline__ uint32_t packf16(float lo, float hi) {
    uint32_t r; asm("cvt.rn.f16x2.f32 %0, %1, %2;" : "=r"(r) : "f"(hi), "f"(lo)); return r;
}
__device__ __forceinline__ float2 unpackf16(uint32_t v) {
    __half2 h = *reinterpret_cast<__half2*>(&v);
    return __half22float2(h);
}
__device__ __forceinline__ void cp16(uint32_t dst, const void* src) {
    asm volatile("cp.async.ca.shared.global [%0], [%1], 16;" :: "r"(dst), "l"(src));
}
__device__ __forceinline__ void cp_commit() { asm volatile("cp.async.commit_group;" ::: "memory"); }
template <int N> __device__ __forceinline__ void cp_wait() {
    asm volatile("cp.async.wait_group %0;" :: "n"(N) : "memory");
}

// ----------------------------------------------------------------------------
// Conversion kernels
// ----------------------------------------------------------------------------
__global__ void split_kernel(const float* __restrict__ in,
                             __half* __restrict__ hi, __half* __restrict__ lo, int n4) {
    int i = blockIdx.x * blockDim.x + threadIdx.x;
    if (i >= n4) return;
    float4 v = ((const float4*)in)[i];
    uint32_t h0 = packf16(v.x, v.y), h1 = packf16(v.z, v.w);
    float2 f0 = unpackf16(h0), f1 = unpackf16(h1);
    uint32_t l0 = packf16(v.x - f0.x, v.y - f0.y);
    uint32_t l1 = packf16(v.z - f1.x, v.w - f1.y);
    ((uint32_t*)hi)[2 * i] = h0; ((uint32_t*)hi)[2 * i + 1] = h1;
    ((uint32_t*)lo)[2 * i] = l0; ((uint32_t*)lo)[2 * i + 1] = l1;
}

// W [K,N] fp32 -> T [N,K] fp16 (single precision level)
__global__ void transpose_kernel(const float* __restrict__ W,
                                 __half* __restrict__ T, int K, int N) {
    __shared__ float tile[32][33];
    const int bx = blockIdx.x * 32, by = blockIdx.y * 32;
    const int tx = threadIdx.x, ty = threadIdx.y;
#pragma unroll
    for (int i = 0; i < 32; i += 8)
        tile[ty + i][tx] = W[(by + ty + i) * N + bx + tx];
    __syncthreads();
#pragma unroll
    for (int i = 0; i < 32; i += 8)
        T[(bx + ty + i) * K + by + tx] = __float2half(tile[tx][ty + i]);
}

// ----------------------------------------------------------------------------
// 2-pass fp16 HMMA GEMM: C = Ah@B^T + Al@B^T + bias
// A*: [M,K] fp16 row-major.  B: [N,K] fp16 row-major.  Out fp32 C or fp16 Ch.
// 128x128x32 tile, 256 threads, XOR-swizzled SMEM [Ah|Al|B], cp.async 2-buffer.
// ----------------------------------------------------------------------------
#define GBM 128
#define GBN 128
#define GBK 32
#define MATB 8192
#define BUFB (3 * MATB)
#define GSMEM (2 * BUFB)    // 48 KB

__global__ __launch_bounds__(256, 2)
void gemm_tc_kernel(const __half* __restrict__ Ah, const __half* __restrict__ Al,
                    const __half* __restrict__ Bw,
                    const float* __restrict__ bias, float* __restrict__ C,
                    __half* __restrict__ Ch, int M, int N, int K)
{
    extern __shared__ __align__(16) char gsm[];
    const uint32_t sb = s2u(gsm);
    const int t = threadIdx.x, lane = t & 31, warp = t >> 5;
    const int wm = warp & 1, wn = warp >> 1;
    const int bm = blockIdx.y * GBM, bn = blockIdx.x * GBN;

    const int srow = t >> 2;
    const int squad = t & 3;
    const uint32_t sq = (uint32_t)(squad ^ ((srow >> 1) & 3));
    const __half* a0 = Ah + (ull)(bm + srow) * K + squad * 8;
    const __half* b0 = Bw + (ull)(bn + srow) * K + squad * 8;
    const long dal = (long)(Al - Ah);
    const uint32_t sdst = sb + (uint32_t)srow * 64 + sq * 16;

    auto stage = [&](int kt, int buf) {
        const uint32_t d0 = sdst + (uint32_t)buf * BUFB;
        const __half* ap = a0 + kt * GBK;
        const __half* bp = b0 + kt * GBK;
        cp16(d0,                      ap);
        cp16(d0 + 4096,               ap + (ull)64 * K);
        cp16(d0 + MATB,               ap + dal);
        cp16(d0 + MATB + 4096,        ap + dal + (ull)64 * K);
        cp16(d0 + 2 * MATB,           bp);
        cp16(d0 + 2 * MATB + 4096,    bp + (ull)64 * K);
    };

    const int rA = wm * 64 + (lane & 15);
    const uint32_t fA = (uint32_t)((rA >> 1) & 3);
    const int hA = lane >> 4;
    const int rB = wn * 32 + (lane & 7) + (lane >> 4) * 8;
    const uint32_t fB = (uint32_t)((rB >> 1) & 3);
    const int hB = (lane >> 3) & 1;

    float acc[4][4][4];
#pragma unroll
    for (int mi = 0; mi < 4; mi++)
#pragma unroll
        for (int ni = 0; ni < 4; ni++)
#pragma unroll
            for (int j = 0; j < 4; j++) acc[mi][ni][j] = 0.0f;

    stage(0, 0); cp_commit();
    const int nkt = K / GBK;

    for (int kt = 0; kt < nkt; kt++) {
        const int cur = kt & 1;
        if (kt + 1 < nkt) { stage(kt + 1, cur ^ 1); cp_commit(); cp_wait<1>(); }
        else cp_wait<0>();
        __syncthreads();

        const uint32_t bb = sb + (uint32_t)cur * BUFB;
#pragma unroll
        for (int ks = 0; ks < 2; ks++) {
            uint32_t bh[2][4];
            const uint32_t qa = (((uint32_t)(2 * ks + hA)) ^ fA) * 16;
            const uint32_t qb = (((uint32_t)(2 * ks + hB)) ^ fB) * 16;
            const uint32_t arow = bb + (uint32_t)rA * 64 + qa;
            const uint32_t brow = bb + 2 * MATB + (uint32_t)rB * 64 + qb;
#pragma unroll
            for (int np = 0; np < 2; np++)
                ldm_x4(bh[np], brow + np * 1024);
#pragma unroll
            for (int mi = 0; mi < 4; mi++) {
                uint32_t ah[4], al[4];
                ldm_x4(ah, arow + mi * 1024);
                ldm_x4(al, arow + MATB + mi * 1024);
#pragma unroll
                for (int ni = 0; ni < 4; ni++)
                    mma16(acc[mi][ni], ah, &bh[ni >> 1][(ni & 1) * 2]);
#pragma unroll
                for (int ni = 0; ni < 4; ni++)
                    mma16(acc[mi][ni], al, &bh[ni >> 1][(ni & 1) * 2]);
            }
        }
        __syncthreads();
    }

    // epilogue
    const int rbase = bm + wm * 64 + (lane >> 2);
    const int cbase = bn + wn * 32 + (lane & 3) * 2;
#pragma unroll
    for (int mi = 0; mi < 4; mi++) {
#pragma unroll
        for (int ni = 0; ni < 4; ni++) {
            const int col = cbase + ni * 8;
            const float bz0 = bias[col], bz1 = bias[col + 1];
            const int r0 = rbase + mi * 16;
            float o00 = acc[mi][ni][0] + bz0, o01 = acc[mi][ni][1] + bz1;
            float o10 = acc[mi][ni][2] + bz0, o11 = acc[mi][ni][3] + bz1;
            if (Ch) {
                *(uint32_t*)(Ch + (ull)r0 * N + col)       = packf16(o00, o01);
                *(uint32_t*)(Ch + (ull)(r0 + 8) * N + col) = packf16(o10, o11);
            } else {
                float2 ax; ax.x = o00; ax.y = o01;
                float2 ay; ay.x = o10; ay.y = o11;
                *(float2*)(C + (ull)r0 * N + col) = ax;
                *(float2*)(C + (ull)(r0 + 8) * N + col) = ay;
            }
        }
    }
}

// ----------------------------------------------------------------------------
// fp16 HMMA causal flash attention: QK 1-pass, PV 2-pass (P hi/lo, V reused).
// Stages only K and V (single fp16). Writes sa hi/lo fp16.
// ----------------------------------------------------------------------------
#define LQ 72
#define QS_ELEMS (128 * LQ)
#define MAT_ELEMS (64 * LQ)
#define ATTN_SMEM ((QS_ELEMS + 2 * 2 * MAT_ELEMS) * 2)

__global__ __launch_bounds__(256)
void attn_kernel()
{
    extern __shared__ __align__(16) __half sm[];
    __half* Qs = sm;
    __half* KV = sm + QS_ELEMS;   // [buf][2][64*LQ]  (K, V)

    const int t = threadIdx.x, lane = t & 31, w = t >> 5;
    const int qi = 15 - (int)blockIdx.x;
    const int bh = blockIdx.y, b = bh >> 4, h = bh & 15;
    const __half* GH = g_qkv + (ull)b * (S_ * H3) + (ull)h * (S_ * CH);
    const int qbase = qi * 128;

#pragma unroll
    for (int i = t; i < 128 * 8; i += 256) {
        int row = i >> 3, seg = i & 7;
        *(uint4*)(Qs + row * LQ + seg * 8) =
            *(const uint4*)(GH + (ull)(qbase + row) * CH + seg * 8);
    }

    const uint32_t kvB = s2u(KV);
    auto stage = [&](int kt, int buf) {
        const int j0 = kt * 64;
        const uint32_t dstb = kvB + buf * (2 * MAT_ELEMS * 2);
#pragma unroll
        for (int i = t; i < 2 * 64 * 8; i += 256) {
            int mmat = i >> 9;            // 0 = K, 1 = V
            int row = (i >> 3) & 63;
            int seg = i & 7;
            const __half* src = GH + (ull)(j0 + row) * CH + 64 + mmat * 64 + seg * 8;
            cp16(dstb + (mmat * MAT_ELEMS + row * LQ + seg * 8) * 2, src);
        }
    };

    stage(0, 0); cp_commit();

    const int nkt = 2 * (qi + 1);
    const int r0g = qbase + w * 16 + (lane >> 2);
    const int r1g = r0g + 8;
    const float scale = 0.02209708691f;   // (2*1024)^-0.5

    float m0 = -1e30f, m1 = -1e30f, l0 = 0.0f, l1 = 0.0f;
    float co[8][4];
#pragma unroll
    for (int i = 0; i < 8; i++)
#pragma unroll
        for (int j = 0; j < 4; j++) co[i][j] = 0.0f;

    uint32_t qf[4][4];
    bool qloaded = false;
    const uint32_t qaddr0 = s2u(Qs) + ((uint32_t)(w * 16 + (lane & 15)) * LQ + (lane >> 4) * 8) * 2;

    for (int kt = 0; kt < nkt; kt++) {
        const int cur = kt & 1;
        if (kt + 1 < nkt) { stage(kt + 1, cur ^ 1); cp_commit(); cp_wait<1>(); }
        else cp_wait<0>();
        __syncthreads();

        if (!qloaded) {
#pragma unroll
            for (int ks = 0; ks < 4; ks++) ldm_x4(qf[ks], qaddr0 + ks * 32);
            qloaded = true;
        }

        const uint32_t bufb = kvB + cur * (2 * MAT_ELEMS * 2);
        const uint32_t KhB = bufb, VhB = bufb + MAT_ELEMS * 2;

        // ---- S = Q @ K^T (single pass) ----
        float cs[8][4];
#pragma unroll
        for (int i = 0; i < 8; i++)
#pragma unroll
            for (int j = 0; j < 4; j++) cs[i][j] = 0.0f;

        const uint32_t kfoff = ((uint32_t)((lane & 7) + ((lane >> 4) & 1) * 8) * LQ
                                + ((lane >> 3) & 1) * 8) * 2;
#pragma unroll
        for (int ks = 0; ks < 4; ks++) {
#pragma unroll
            for (int nip = 0; nip < 4; nip++) {
                uint32_t bfr[4];
                ldm_x4(bfr, KhB + kfoff + ((uint32_t)nip * 16 * LQ + ks * 16) * 2);
                mma16(cs[2 * nip],     qf[ks], bfr);
                mma16(cs[2 * nip + 1], qf[ks], bfr + 2);
            }
        }

        // ---- mask + scale + online softmax ----
        const int cb = kt * 64 + 2 * (lane & 3);
        float sv0[16], sv1[16];
        float tm0 = -1e30f, tm1 = -1e30f;
#pragma unroll
        for (int ni = 0; ni < 8; ni++) {
#pragma unroll
            for (int e = 0; e < 2; e++) {
                const int col = cb + ni * 8 + e;
                float v0 = (col <= r0g) ? cs[ni][e]     * scale : -1e30f;
                float v1 = (col <= r1g) ? cs[ni][2 + e] * scale : -1e30f;
                sv0[ni * 2 + e] = v0; sv1[ni * 2 + e] = v1;
                tm0 = fmaxf(tm0, v0); tm1 = fmaxf(tm1, v1);
            }
        }
        tm0 = fmaxf(tm0, __shfl_xor_sync(0xffffffffu, tm0, 1));
        tm0 = fmaxf(tm0, __shfl_xor_sync(0xffffffffu, tm0, 2));
        tm1 = fmaxf(tm1, __shfl_xor_sync(0xffffffffu, tm1, 1));
        tm1 = fmaxf(tm1, __shfl_xor_sync(0xffffffffu, tm1, 2));
        const float mn0 = fmaxf(m0, tm0), mn1 = fmaxf(m1, tm1);
        const float corr0 = __expf(m0 - mn0), corr1 = __expf(m1 - mn1);
        m0 = mn0; m1 = mn1;
        float ps0 = 0.0f, ps1 = 0.0f;
#pragma unroll
        for (int i = 0; i < 16; i++) {
            sv0[i] = __expf(sv0[i] - mn0); ps0 += sv0[i];
            sv1[i] = __expf(sv1[i] - mn1); ps1 += sv1[i];
        }
        ps0 += __shfl_xor_sync(0xffffffffu, ps0, 1);
        ps0 += __shfl_xor_sync(0xffffffffu, ps0, 2);
        ps1 += __shfl_xor_sync(0xffffffffu, ps1, 1);
        ps1 += __shfl_xor_sync(0xffffffffu, ps1, 2);
        l0 = l0 * corr0 + ps0;
        l1 = l1 * corr1 + ps1;
#pragma unroll
        for (int nd = 0; nd < 8; nd++) {
            co[nd][0] *= corr0; co[nd][1] *= corr0;
            co[nd][2] *= corr1; co[nd][3] *= corr1;
        }

        // ---- P hi/lo fp16 A-fragments straight from S fragments ----
        uint32_t ph[4][4], pl[4][4];
#pragma unroll
        for (int kj = 0; kj < 4; kj++) {
            uint32_t a0 = packf16(sv0[4 * kj],     sv0[4 * kj + 1]);
            uint32_t a1 = packf16(sv1[4 * kj],     sv1[4 * kj + 1]);
            uint32_t a2 = packf16(sv0[4 * kj + 2], sv0[4 * kj + 3]);
            uint32_t a3 = packf16(sv1[4 * kj + 2], sv1[4 * kj + 3]);
            ph[kj][0] = a0; ph[kj][1] = a1; ph[kj][2] = a2; ph[kj][3] = a3;
            float2 f0 = unpackf16(a0), f1 = unpackf16(a1);
            float2 f2 = unpackf16(a2), f3 = unpackf16(a3);
            pl[kj][0] = packf16(sv0[4 * kj] - f0.x,     sv0[4 * kj + 1] - f0.y);
            pl[kj][1] = packf16(sv1[4 * kj] - f1.x,     sv1[4 * kj + 1] - f1.y);
            pl[kj][2] = packf16(sv0[4 * kj + 2] - f2.x, sv0[4 * kj + 3] - f2.y);
            pl[kj][3] = packf16(sv1[4 * kj + 2] - f3.x, sv1[4 * kj + 3] - f3.y);
        }

        // ---- O += (Ph + Pl) @ V  (V fragments loaded once, reused) ----
        const uint32_t vfoff = ((uint32_t)(lane & 15) * LQ) * 2 + (lane >> 4) * 16;
#pragma unroll
        for (int kj = 0; kj < 4; kj++) {
#pragma unroll
            for (int ndp = 0; ndp < 4; ndp++) {
                uint32_t bfr[4];
                ldm_x4_t(bfr, VhB + vfoff + (uint32_t)kj * 16 * LQ * 2 + ndp * 32);
                mma16(co[2 * ndp],     ph[kj], bfr);
                mma16(co[2 * ndp + 1], ph[kj], bfr + 2);
                mma16(co[2 * ndp],     pl[kj], bfr);
                mma16(co[2 * ndp + 1], pl[kj], bfr + 2);
            }
        }
        __syncthreads();
    }

    // ---- normalize, split hi/lo fp16, store to scrambled sa layout ----
    const float il0 = 1.0f / l0, il1 = 1.0f / l1;
    const ull row0 = (ull)(b * S_ + h * 128 + (r0g >> 4)) * E_ + (r0g & 15) * 64;
    const ull row1 = (ull)(b * S_ + h * 128 + (r1g >> 4)) * E_ + (r1g & 15) * 64;
    const int dcol = 2 * (lane & 3);
#pragma unroll
    for (int nd = 0; nd < 8; nd++) {
        const int d = nd * 8 + dcol;
        float o00 = co[nd][0] * il0, o01 = co[nd][1] * il0;
        float o10 = co[nd][2] * il1, o11 = co[nd][3] * il1;
        uint32_t h0 = packf16(o00, o01);
        uint32_t h1 = packf16(o10, o11);
        float2 f0 = unpackf16(h0), f1 = unpackf16(h1);
        uint32_t q0 = packf16(o00 - f0.x, o01 - f0.y);
        uint32_t q1 = packf16(o10 - f1.x, o11 - f1.y);
        *(uint32_t*)(g_sah + row0 + d) = h0;
        *(uint32_t*)(g_sah + row1 + d) = h1;
        *(uint32_t*)(g_sal + row0 + d) = q0;
        *(uint32_t*)(g_sal + row1 + d) = q1;
    }
}

// ----------------------------------------------------------------------------
extern "C" void kernel_launch(void* const* d_in, const int* in_sizes, int n_in,
                              void* d_out, int out_size)
{
    const float* x     = (const float*)d_in[0];
    const float* W_qkv = (const float*)d_in[1];
    const float* b_qkv = (const float*)d_in[2];
    const float* W_out = (const float*)d_in[3];
    const float* b_out = (const float*)d_in[4];
    float* out = (float*)d_out;

    __half *qkv, *xh, *xl, *wq, *wo, *sah, *sal;
    cudaGetSymbolAddress((void**)&qkv, g_qkv);
    cudaGetSymbolAddress((void**)&xh, g_xh);   cudaGetSymbolAddress((void**)&xl, g_xl);
    cudaGetSymbolAddress((void**)&wq, g_wq);   cudaGetSymbolAddress((void**)&wo, g_wo);
    cudaGetSymbolAddress((void**)&sah, g_sah); cudaGetSymbolAddress((void**)&sal, g_sal);

    cudaFuncSetAttribute(attn_kernel,
                         cudaFuncAttributeMaxDynamicSharedMemorySize, ATTN_SMEM);
    cudaFuncSetAttribute(gemm_tc_kernel,
                         cudaFuncAttributeMaxDynamicSharedMemorySize, GSMEM);

    // 0) operand prep
    {
        const int n4 = MROWS * E_ / 4;
        split_kernel<<<(n4 + 255) / 256, 256>>>(x, xh, xl, n4);
        transpose_kernel<<<dim3(H3 / 32, E_ / 32), dim3(32, 8)>>>(W_qkv, wq, E_, H3);
        transpose_kernel<<<dim3(E_ / 32, E_ / 32), dim3(32, 8)>>>(W_out, wo, E_, E_);
    }

    // 1) QKV projection (2-pass) -> single fp16 qkv
    gemm_tc_kernel<<<dim3(H3 / GBN, MROWS / GBM), 256, GSMEM>>>(
        xh, xl, wq, b_qkv, nullptr, qkv, MROWS, H3, E_);

    // 2) fp16 HMMA causal attention -> hi/lo fp16 sa
    attn_kernel<<<dim3(16, B_ * NH), 256, ATTN_SMEM>>>();

    // 3) output projection (2-pass) -> fp32 out
    gemm_tc_kernel<<<dim3(E_ / GBN, MROWS / GBM), 256, GSMEM>>>(
        sah, sal, wo, b_out, out, nullptr, MROWS, E_, E_);
}

// round 15
// speedup vs baseline: 1.4875x; 1.0091x over previous
#include <cuda_runtime.h>
#include <cuda_fp16.h>
#include <cstdint>

// ----------------------------------------------------------------------------
// MaskedMSA: x@Wqkv+b -> (faithful reshape) -> causal MHA -> sa@Wout+b
// B=4, S=2048, E=1024, HIDDEN=1024, HEADS=16, d_head=64
// fp16 HMMA everywhere. GEMM1: Ah pass on all columns, Al correction pass ONLY
// on v columns (softmax attenuates q/k error ~20x). GEMM3: full 2-pass.
// Attention: QK 1-pass, PV 2-pass via P hi/lo split.
// ----------------------------------------------------------------------------

#define B_  4
#define S_  2048
#define E_  1024
#define H3  3072
#define NH  16
#define CH  192
#define MROWS (B_ * S_)   // 8192

typedef unsigned long long ull;

// ---------------- scratch (no cudaMalloc allowed) ----------------
__device__ __half g_qkv[MROWS * H3];     // qkv, single fp16
__device__ __half g_xh[MROWS * E_];      // x hi/lo fp16
__device__ __half g_xl[MROWS * E_];
__device__ __half g_wq[H3 * E_];         // W_qkv^T fp16 (single)
__device__ __half g_wo[E_ * E_];         // W_out^T fp16 (single)
__device__ __half g_sah[MROWS * E_];     // attention out hi/lo fp16
__device__ __half g_sal[MROWS * E_];

// ---------------- helpers ----------------
__device__ __forceinline__ uint32_t s2u(const void* p) {
    uint32_t a;
    asm("{ .reg .u64 t; cvta.to.shared.u64 t, %1; cvt.u32.u64 %0, t; }" : "=r"(a) : "l"(p));
    return a;
}
__device__ __forceinline__ void ldm_x4(uint32_t* r, uint32_t addr) {
    asm volatile("ldmatrix.sync.aligned.m8n8.x4.shared.b16 {%0,%1,%2,%3}, [%4];"
                 : "=r"(r[0]), "=r"(r[1]), "=r"(r[2]), "=r"(r[3]) : "r"(addr));
}
__device__ __forceinline__ void ldm_x4_t(uint32_t* r, uint32_t addr) {
    asm volatile("ldmatrix.sync.aligned.m8n8.x4.trans.shared.b16 {%0,%1,%2,%3}, [%4];"
                 : "=r"(r[0]), "=r"(r[1]), "=r"(r[2]), "=r"(r[3]) : "r"(addr));
}
__device__ __forceinline__ void mma16(float* d, const uint32_t* a, const uint32_t* b) {
    asm volatile("mma.sync.aligned.m16n8k16.row.col.f32.f16.f16.f32 "
                 "{%0,%1,%2,%3}, {%4,%5,%6,%7}, {%8,%9}, {%0,%1,%2,%3};"
                 : "+f"(d[0]), "+f"(d[1]), "+f"(d[2]), "+f"(d[3])
                 : "r"(a[0]), "r"(a[1]), "r"(a[2]), "r"(a[3]), "r"(b[0]), "r"(b[1]));
}
// pack (lo, hi) floats into f16x2 (lo in bits[15:0])
__device__ __forceinline__ uint32_t packf16(float lo, float hi) {
    uint32_t r; asm("cvt.rn.f16x2.f32 %0, %1, %2;" : "=r"(r) : "f"(hi), "f"(lo)); return r;
}
__device__ __forceinline__ float2 unpackf16(uint32_t v) {
    __half2 h = *reinterpret_cast<__half2*>(&v);
    return __half22float2(h);
}
__device__ __forceinline__ void cp16(uint32_t dst, const void* src) {
    asm volatile("cp.async.ca.shared.global [%0], [%1], 16;" :: "r"(dst), "l"(src));
}
__device__ __forceinline__ void cp_commit() { asm volatile("cp.async.commit_group;" ::: "memory"); }
template <int N> __device__ __forceinline__ void cp_wait() {
    asm volatile("cp.async.wait_group %0;" :: "n"(N) : "memory");
}

// ----------------------------------------------------------------------------
// Conversion kernels
// ----------------------------------------------------------------------------
__global__ void split_kernel(const float* __restrict__ in,
                             __half* __restrict__ hi, __half* __restrict__ lo, int n4) {
    int i = blockIdx.x * blockDim.x + threadIdx.x;
    if (i >= n4) return;
    float4 v = ((const float4*)in)[i];
    uint32_t h0 = packf16(v.x, v.y), h1 = packf16(v.z, v.w);
    float2 f0 = unpackf16(h0), f1 = unpackf16(h1);
    uint32_t l0 = packf16(v.x - f0.x, v.y - f0.y);
    uint32_t l1 = packf16(v.z - f1.x, v.w - f1.y);
    ((uint32_t*)hi)[2 * i] = h0; ((uint32_t*)hi)[2 * i + 1] = h1;
    ((uint32_t*)lo)[2 * i] = l0; ((uint32_t*)lo)[2 * i + 1] = l1;
}

// W [K,N] fp32 -> T [N,K] fp16 (single precision level)
__global__ void transpose_kernel(const float* __restrict__ W,
                                 __half* __restrict__ T, int K, int N) {
    __shared__ float tile[32][33];
    const int bx = blockIdx.x * 32, by = blockIdx.y * 32;
    const int tx = threadIdx.x, ty = threadIdx.y;
#pragma unroll
    for (int i = 0; i < 32; i += 8)
        tile[ty + i][tx] = W[(by + ty + i) * N + bx + tx];
    __syncthreads();
#pragma unroll
    for (int i = 0; i < 32; i += 8)
        T[(bx + ty + i) * K + by + tx] = __float2half(tile[tx][ty + i]);
}

// ----------------------------------------------------------------------------
// fp16 HMMA GEMM: C = Ah@B^T (+ Al@B^T on selected columns) + bias
// vmode=0: Al pass on ALL columns (GEMM3).
// vmode=1: Al pass only on columns with (col % 192) >= 128 (v columns of qkv).
//          Warp windows (32 cols, 32-aligned vs 192) are uniformly v or not.
// 128x128x32 tile, 256 threads, XOR-swizzled SMEM [Ah|Al|B], cp.async 2-buffer.
// ----------------------------------------------------------------------------
#define GBM 128
#define GBN 128
#define GBK 32
#define MATB 8192
#define BUFB (3 * MATB)
#define GSMEM (2 * BUFB)    // 48 KB

__global__ __launch_bounds__(256, 2)
void gemm_tc_kernel(const __half* __restrict__ Ah, const __half* __restrict__ Al,
                    const __half* __restrict__ Bw,
                    const float* __restrict__ bias, float* __restrict__ C,
                    __half* __restrict__ Ch, int vmode, int M, int N, int K)
{
    extern __shared__ __align__(16) char gsm[];
    const uint32_t sb = s2u(gsm);
    const int t = threadIdx.x, lane = t & 31, warp = t >> 5;
    const int wm = warp & 1, wn = warp >> 1;
    const int bm = blockIdx.y * GBM, bn = blockIdx.x * GBN;

    // Al-pass predicates (uniform per warp / per CTA)
    const bool doAl  = (vmode == 0) || (((bn + wn * 32) % 192) >= 128);
    bool ctaAl = (vmode == 0);
#pragma unroll
    for (int w2 = 0; w2 < 4; w2++)
        if (((bn + w2 * 32) % 192) >= 128) ctaAl = true;

    const int srow = t >> 2;
    const int squad = t & 3;
    const uint32_t sq = (uint32_t)(squad ^ ((srow >> 1) & 3));
    const __half* a0 = Ah + (ull)(bm + srow) * K + squad * 8;
    const __half* b0 = Bw + (ull)(bn + srow) * K + squad * 8;
    const long dal = (long)(Al - Ah);
    const uint32_t sdst = sb + (uint32_t)srow * 64 + sq * 16;

    auto stage = [&](int kt, int buf) {
        const uint32_t d0 = sdst + (uint32_t)buf * BUFB;
        const __half* ap = a0 + kt * GBK;
        const __half* bp = b0 + kt * GBK;
        cp16(d0,                      ap);
        cp16(d0 + 4096,               ap + (ull)64 * K);
        if (ctaAl) {
            cp16(d0 + MATB,           ap + dal);
            cp16(d0 + MATB + 4096,    ap + dal + (ull)64 * K);
        }
        cp16(d0 + 2 * MATB,           bp);
        cp16(d0 + 2 * MATB + 4096,    bp + (ull)64 * K);
    };

    const int rA = wm * 64 + (lane & 15);
    const uint32_t fA = (uint32_t)((rA >> 1) & 3);
    const int hA = lane >> 4;
    const int rB = wn * 32 + (lane & 7) + (lane >> 4) * 8;
    const uint32_t fB = (uint32_t)((rB >> 1) & 3);
    const int hB = (lane >> 3) & 1;

    float acc[4][4][4];
#pragma unroll
    for (int mi = 0; mi < 4; mi++)
#pragma unroll
        for (int ni = 0; ni < 4; ni++)
#pragma unroll
            for (int j = 0; j < 4; j++) acc[mi][ni][j] = 0.0f;

    stage(0, 0); cp_commit();
    const int nkt = K / GBK;

    for (int kt = 0; kt < nkt; kt++) {
        const int cur = kt & 1;
        if (kt + 1 < nkt) { stage(kt + 1, cur ^ 1); cp_commit(); cp_wait<1>(); }
        else cp_wait<0>();
        __syncthreads();

        const uint32_t bb = sb + (uint32_t)cur * BUFB;
#pragma unroll
        for (int ks = 0; ks < 2; ks++) {
            uint32_t bh[2][4];
            const uint32_t qa = (((uint32_t)(2 * ks + hA)) ^ fA) * 16;
            const uint32_t qb = (((uint32_t)(2 * ks + hB)) ^ fB) * 16;
            const uint32_t arow = bb + (uint32_t)rA * 64 + qa;
            const uint32_t brow = bb + 2 * MATB + (uint32_t)rB * 64 + qb;
#pragma unroll
            for (int np = 0; np < 2; np++)
                ldm_x4(bh[np], brow + np * 1024);
#pragma unroll
            for (int mi = 0; mi < 4; mi++) {
                uint32_t ah[4];
                ldm_x4(ah, arow + mi * 1024);
#pragma unroll
                for (int ni = 0; ni < 4; ni++)
                    mma16(acc[mi][ni], ah, &bh[ni >> 1][(ni & 1) * 2]);
                if (doAl) {
                    uint32_t al[4];
                    ldm_x4(al, arow + MATB + mi * 1024);
#pragma unroll
                    for (int ni = 0; ni < 4; ni++)
                        mma16(acc[mi][ni], al, &bh[ni >> 1][(ni & 1) * 2]);
                }
            }
        }
        __syncthreads();
    }

    // epilogue
    const int rbase = bm + wm * 64 + (lane >> 2);
    const int cbase = bn + wn * 32 + (lane & 3) * 2;
#pragma unroll
    for (int mi = 0; mi < 4; mi++) {
#pragma unroll
        for (int ni = 0; ni < 4; ni++) {
            const int col = cbase + ni * 8;
            const float bz0 = bias[col], bz1 = bias[col + 1];
            const int r0 = rbase + mi * 16;
            float o00 = acc[mi][ni][0] + bz0, o01 = acc[mi][ni][1] + bz1;
            float o10 = acc[mi][ni][2] + bz0, o11 = acc[mi][ni][3] + bz1;
            if (Ch) {
                *(uint32_t*)(Ch + (ull)r0 * N + col)       = packf16(o00, o01);
                *(uint32_t*)(Ch + (ull)(r0 + 8) * N + col) = packf16(o10, o11);
            } else {
                float2 ax; ax.x = o00; ax.y = o01;
                float2 ay; ay.x = o10; ay.y = o11;
                *(float2*)(C + (ull)r0 * N + col) = ax;
                *(float2*)(C + (ull)(r0 + 8) * N + col) = ay;
            }
        }
    }
}

// ----------------------------------------------------------------------------
// fp16 HMMA causal flash attention: QK 1-pass, PV 2-pass (P hi/lo, V reused).
// ----------------------------------------------------------------------------
#define LQ 72
#define QS_ELEMS (128 * LQ)
#define MAT_ELEMS (64 * LQ)
#define ATTN_SMEM ((QS_ELEMS + 2 * 2 * MAT_ELEMS) * 2)

__global__ __launch_bounds__(256)
void attn_kernel()
{
    extern __shared__ __align__(16) __half sm[];
    __half* Qs = sm;
    __half* KV = sm + QS_ELEMS;   // [buf][2][64*LQ]  (K, V)

    const int t = threadIdx.x, lane = t & 31, w = t >> 5;
    const int qi = 15 - (int)blockIdx.x;
    const int bh = blockIdx.y, b = bh >> 4, h = bh & 15;
    const __half* GH = g_qkv + (ull)b * (S_ * H3) + (ull)h * (S_ * CH);
    const int qbase = qi * 128;

#pragma unroll
    for (int i = t; i < 128 * 8; i += 256) {
        int row = i >> 3, seg = i & 7;
        *(uint4*)(Qs + row * LQ + seg * 8) =
            *(const uint4*)(GH + (ull)(qbase + row) * CH + seg * 8);
    }

    const uint32_t kvB = s2u(KV);
    auto stage = [&](int kt, int buf) {
        const int j0 = kt * 64;
        const uint32_t dstb = kvB + buf * (2 * MAT_ELEMS * 2);
#pragma unroll
        for (int i = t; i < 2 * 64 * 8; i += 256) {
            int mmat = i >> 9;            // 0 = K, 1 = V
            int row = (i >> 3) & 63;
            int seg = i & 7;
            const __half* src = GH + (ull)(j0 + row) * CH + 64 + mmat * 64 + seg * 8;
            cp16(dstb + (mmat * MAT_ELEMS + row * LQ + seg * 8) * 2, src);
        }
    };

    stage(0, 0); cp_commit();

    const int nkt = 2 * (qi + 1);
    const int r0g = qbase + w * 16 + (lane >> 2);
    const int r1g = r0g + 8;
    const float scale = 0.02209708691f;   // (2*1024)^-0.5

    float m0 = -1e30f, m1 = -1e30f, l0 = 0.0f, l1 = 0.0f;
    float co[8][4];
#pragma unroll
    for (int i = 0; i < 8; i++)
#pragma unroll
        for (int j = 0; j < 4; j++) co[i][j] = 0.0f;

    uint32_t qf[4][4];
    bool qloaded = false;
    const uint32_t qaddr0 = s2u(Qs) + ((uint32_t)(w * 16 + (lane & 15)) * LQ + (lane >> 4) * 8) * 2;

    for (int kt = 0; kt < nkt; kt++) {
        const int cur = kt & 1;
        if (kt + 1 < nkt) { stage(kt + 1, cur ^ 1); cp_commit(); cp_wait<1>(); }
        else cp_wait<0>();
        __syncthreads();

        if (!qloaded) {
#pragma unroll
            for (int ks = 0; ks < 4; ks++) ldm_x4(qf[ks], qaddr0 + ks * 32);
            qloaded = true;
        }

        const uint32_t bufb = kvB + cur * (2 * MAT_ELEMS * 2);
        const uint32_t KhB = bufb, VhB = bufb + MAT_ELEMS * 2;

        // ---- S = Q @ K^T (single pass) ----
        float cs[8][4];
#pragma unroll
        for (int i = 0; i < 8; i++)
#pragma unroll
            for (int j = 0; j < 4; j++) cs[i][j] = 0.0f;

        const uint32_t kfoff = ((uint32_t)((lane & 7) + ((lane >> 4) & 1) * 8) * LQ
                                + ((lane >> 3) & 1) * 8) * 2;
#pragma unroll
        for (int ks = 0; ks < 4; ks++) {
#pragma unroll
            for (int nip = 0; nip < 4; nip++) {
                uint32_t bfr[4];
                ldm_x4(bfr, KhB + kfoff + ((uint32_t)nip * 16 * LQ + ks * 16) * 2);
                mma16(cs[2 * nip],     qf[ks], bfr);
                mma16(cs[2 * nip + 1], qf[ks], bfr + 2);
            }
        }

        // ---- mask + scale + online softmax ----
        const int cb = kt * 64 + 2 * (lane & 3);
        float sv0[16], sv1[16];
        float tm0 = -1e30f, tm1 = -1e30f;
#pragma unroll
        for (int ni = 0; ni < 8; ni++) {
#pragma unroll
            for (int e = 0; e < 2; e++) {
                const int col = cb + ni * 8 + e;
                float v0 = (col <= r0g) ? cs[ni][e]     * scale : -1e30f;
                float v1 = (col <= r1g) ? cs[ni][2 + e] * scale : -1e30f;
                sv0[ni * 2 + e] = v0; sv1[ni * 2 + e] = v1;
                tm0 = fmaxf(tm0, v0); tm1 = fmaxf(tm1, v1);
            }
        }
        tm0 = fmaxf(tm0, __shfl_xor_sync(0xffffffffu, tm0, 1));
        tm0 = fmaxf(tm0, __shfl_xor_sync(0xffffffffu, tm0, 2));
        tm1 = fmaxf(tm1, __shfl_xor_sync(0xffffffffu, tm1, 1));
        tm1 = fmaxf(tm1, __shfl_xor_sync(0xffffffffu, tm1, 2));
        const float mn0 = fmaxf(m0, tm0), mn1 = fmaxf(m1, tm1);
        const float corr0 = __expf(m0 - mn0), corr1 = __expf(m1 - mn1);
        m0 = mn0; m1 = mn1;
        float ps0 = 0.0f, ps1 = 0.0f;
#pragma unroll
        for (int i = 0; i < 16; i++) {
            sv0[i] = __expf(sv0[i] - mn0); ps0 += sv0[i];
            sv1[i] = __expf(sv1[i] - mn1); ps1 += sv1[i];
        }
        ps0 += __shfl_xor_sync(0xffffffffu, ps0, 1);
        ps0 += __shfl_xor_sync(0xffffffffu, ps0, 2);
        ps1 += __shfl_xor_sync(0xffffffffu, ps1, 1);
        ps1 += __shfl_xor_sync(0xffffffffu, ps1, 2);
        l0 = l0 * corr0 + ps0;
        l1 = l1 * corr1 + ps1;
#pragma unroll
        for (int nd = 0; nd < 8; nd++) {
            co[nd][0] *= corr0; co[nd][1] *= corr0;
            co[nd][2] *= corr1; co[nd][3] *= corr1;
        }

        // ---- P hi/lo fp16 A-fragments straight from S fragments ----
        uint32_t ph[4][4], pl[4][4];
#pragma unroll
        for (int kj = 0; kj < 4; kj++) {
            uint32_t a0 = packf16(sv0[4 * kj],     sv0[4 * kj + 1]);
            uint32_t a1 = packf16(sv1[4 * kj],     sv1[4 * kj + 1]);
            uint32_t a2 = packf16(sv0[4 * kj + 2], sv0[4 * kj + 3]);
            uint32_t a3 = packf16(sv1[4 * kj + 2], sv1[4 * kj + 3]);
            ph[kj][0] = a0; ph[kj][1] = a1; ph[kj][2] = a2; ph[kj][3] = a3;
            float2 f0 = unpackf16(a0), f1 = unpackf16(a1);
            float2 f2 = unpackf16(a2), f3 = unpackf16(a3);
            pl[kj][0] = packf16(sv0[4 * kj] - f0.x,     sv0[4 * kj + 1] - f0.y);
            pl[kj][1] = packf16(sv1[4 * kj] - f1.x,     sv1[4 * kj + 1] - f1.y);
            pl[kj][2] = packf16(sv0[4 * kj + 2] - f2.x, sv0[4 * kj + 3] - f2.y);
            pl[kj][3] = packf16(sv1[4 * kj + 2] - f3.x, sv1[4 * kj + 3] - f3.y);
        }

        // ---- O += (Ph + Pl) @ V  (V fragments loaded once, reused) ----
        const uint32_t vfoff = ((uint32_t)(lane & 15) * LQ) * 2 + (lane >> 4) * 16;
#pragma unroll
        for (int kj = 0; kj < 4; kj++) {
#pragma unroll
            for (int ndp = 0; ndp < 4; ndp++) {
                uint32_t bfr[4];
                ldm_x4_t(bfr, VhB + vfoff + (uint32_t)kj * 16 * LQ * 2 + ndp * 32);
                mma16(co[2 * ndp],     ph[kj], bfr);
                mma16(co[2 * ndp + 1], ph[kj], bfr + 2);
                mma16(co[2 * ndp],     pl[kj], bfr);
                mma16(co[2 * ndp + 1], pl[kj], bfr + 2);
            }
        }
        __syncthreads();
    }

    // ---- normalize, split hi/lo fp16, store to scrambled sa layout ----
    const float il0 = 1.0f / l0, il1 = 1.0f / l1;
    const ull row0 = (ull)(b * S_ + h * 128 + (r0g >> 4)) * E_ + (r0g & 15) * 64;
    const ull row1 = (ull)(b * S_ + h * 128 + (r1g >> 4)) * E_ + (r1g & 15) * 64;
    const int dcol = 2 * (lane & 3);
#pragma unroll
    for (int nd = 0; nd < 8; nd++) {
        const int d = nd * 8 + dcol;
        float o00 = co[nd][0] * il0, o01 = co[nd][1] * il0;
        float o10 = co[nd][2] * il1, o11 = co[nd][3] * il1;
        uint32_t h0 = packf16(o00, o01);
        uint32_t h1 = packf16(o10, o11);
        float2 f0 = unpackf16(h0), f1 = unpackf16(h1);
        uint32_t q0 = packf16(o00 - f0.x, o01 - f0.y);
        uint32_t q1 = packf16(o10 - f1.x, o11 - f1.y);
        *(uint32_t*)(g_sah + row0 + d) = h0;
        *(uint32_t*)(g_sah + row1 + d) = h1;
        *(uint32_t*)(g_sal + row0 + d) = q0;
        *(uint32_t*)(g_sal + row1 + d) = q1;
    }
}

// ----------------------------------------------------------------------------
extern "C" void kernel_launch(void* const* d_in, const int* in_sizes, int n_in,
                              void* d_out, int out_size)
{
    const float* x     = (const float*)d_in[0];
    const float* W_qkv = (const float*)d_in[1];
    const float* b_qkv = (const float*)d_in[2];
    const float* W_out = (const float*)d_in[3];
    const float* b_out = (const float*)d_in[4];
    float* out = (float*)d_out;

    __half *qkv, *xh, *xl, *wq, *wo, *sah, *sal;
    cudaGetSymbolAddress((void**)&qkv, g_qkv);
    cudaGetSymbolAddress((void**)&xh, g_xh);   cudaGetSymbolAddress((void**)&xl, g_xl);
    cudaGetSymbolAddress((void**)&wq, g_wq);   cudaGetSymbolAddress((void**)&wo, g_wo);
    cudaGetSymbolAddress((void**)&sah, g_sah); cudaGetSymbolAddress((void**)&sal, g_sal);

    cudaFuncSetAttribute(attn_kernel,
                         cudaFuncAttributeMaxDynamicSharedMemorySize, ATTN_SMEM);
    cudaFuncSetAttribute(gemm_tc_kernel,
                         cudaFuncAttributeMaxDynamicSharedMemorySize, GSMEM);

    // 0) operand prep
    {
        const int n4 = MROWS * E_ / 4;
        split_kernel<<<(n4 + 255) / 256, 256>>>(x, xh, xl, n4);
        transpose_kernel<<<dim3(H3 / 32, E_ / 32), dim3(32, 8)>>>(W_qkv, wq, E_, H3);
        transpose_kernel<<<dim3(E_ / 32, E_ / 32), dim3(32, 8)>>>(W_out, wo, E_, E_);
    }

    // 1) QKV projection (Ah all cols, Al on v cols only) -> single fp16 qkv
    gemm_tc_kernel<<<dim3(H3 / GBN, MROWS / GBM), 256, GSMEM>>>(
        xh, xl, wq, b_qkv, nullptr, qkv, /*vmode=*/1, MROWS, H3, E_);

    // 2) fp16 HMMA causal attention -> hi/lo fp16 sa
    attn_kernel<<<dim3(16, B_ * NH), 256, ATTN_SMEM>>>();

    // 3) output projection (full 2-pass) -> fp32 out
    gemm_tc_kernel<<<dim3(E_ / GBN, MROWS / GBM), 256, GSMEM>>>(
        sah, sal, wo, b_out, out, nullptr, /*vmode=*/0, MROWS, E_, E_);
}

// round 16
// speedup vs baseline: 1.5439x; 1.0379x over previous
#include <cuda_runtime.h>
#include <cuda_fp16.h>
#include <cstdint>

// ----------------------------------------------------------------------------
// MaskedMSA: x@Wqkv+b -> (faithful reshape) -> causal MHA -> sa@Wout+b
// B=4, S=2048, E=1024, HIDDEN=1024, HEADS=16, d_head=64
// fp16 HMMA. qkv computed into COLUMN-PERMUTED split buffers:
//   g_qk [8192, 2048]  (q,k cols; 1-pass GEMM — softmax attenuates error)
//   g_v  [8192, 1024]  (v cols; 2-pass GEMM — linear path)
// Attention: QK 1-pass, PV 2-pass via P hi/lo split. GEMM3: 2-pass.
// ----------------------------------------------------------------------------

#define B_  4
#define S_  2048
#define E_  1024
#define H3  3072
#define NH  16
#define MROWS (B_ * S_)   // 8192

typedef unsigned long long ull;

// ---------------- scratch (no cudaMalloc allowed) ----------------
__device__ __half g_qk[MROWS * 2048];    // permuted q,k  (head h: block S*128)
__device__ __half g_v [MROWS * 1024];    // permuted v    (head h: block S*64)
__device__ __half g_xh[MROWS * E_];      // x hi/lo fp16
__device__ __half g_xl[MROWS * E_];
__device__ __half g_wqk[2048 * E_];      // permuted W_qkv^T (qk rows)
__device__ __half g_wv [1024 * E_];      // permuted W_qkv^T (v rows)
__device__ __half g_wo[E_ * E_];         // W_out^T fp16
__device__ float  g_bqk[2048];           // permuted bias
__device__ float  g_bv [1024];
__device__ __half g_sah[MROWS * E_];     // attention out hi/lo fp16
__device__ __half g_sal[MROWS * E_];

// ---------------- helpers ----------------
__device__ __forceinline__ uint32_t s2u(const void* p) {
    uint32_t a;
    asm("{ .reg .u64 t; cvta.to.shared.u64 t, %1; cvt.u32.u64 %0, t; }" : "=r"(a) : "l"(p));
    return a;
}
__device__ __forceinline__ void ldm_x4(uint32_t* r, uint32_t addr) {
    asm volatile("ldmatrix.sync.aligned.m8n8.x4.shared.b16 {%0,%1,%2,%3}, [%4];"
                 : "=r"(r[0]), "=r"(r[1]), "=r"(r[2]), "=r"(r[3]) : "r"(addr));
}
__device__ __forceinline__ void ldm_x4_t(uint32_t* r, uint32_t addr) {
    asm volatile("ldmatrix.sync.aligned.m8n8.x4.trans.shared.b16 {%0,%1,%2,%3}, [%4];"
                 : "=r"(r[0]), "=r"(r[1]), "=r"(r[2]), "=r"(r[3]) : "r"(addr));
}
__device__ __forceinline__ void mma16(float* d, const uint32_t* a, const uint32_t* b) {
    asm volatile("mma.sync.aligned.m16n8k16.row.col.f32.f16.f16.f32 "
                 "{%0,%1,%2,%3}, {%4,%5,%6,%7}, {%8,%9}, {%0,%1,%2,%3};"
                 : "+f"(d[0]), "+f"(d[1]), "+f"(d[2]), "+f"(d[3])
                 : "r"(a[0]), "r"(a[1]), "r"(a[2]), "r"(a[3]), "r"(b[0]), "r"(b[1]));
}
__device__ __forceinline__ uint32_t packf16(float lo, float hi) {
    uint32_t r; asm("cvt.rn.f16x2.f32 %0, %1, %2;" : "=r"(r) : "f"(hi), "f"(lo)); return r;
}
__device__ __forceinline__ float2 unpackf16(uint32_t v) {
    __half2 h = *reinterpret_cast<__half2*>(&v);
    return __half22float2(h);
}
__device__ __forceinline__ void cp16(uint32_t dst, const void* src) {
    asm volatile("cp.async.ca.shared.global [%0], [%1], 16;" :: "r"(dst), "l"(src));
}
__device__ __forceinline__ void cp_commit() { asm volatile("cp.async.commit_group;" ::: "memory"); }
template <int N> __device__ __forceinline__ void cp_wait() {
    asm volatile("cp.async.wait_group %0;" :: "n"(N) : "memory");
}

// ----------------------------------------------------------------------------
// Prep kernels
// ----------------------------------------------------------------------------
__global__ void split_kernel(const float* __restrict__ in,
                             __half* __restrict__ hi, __half* __restrict__ lo, int n4) {
    int i = blockIdx.x * blockDim.x + threadIdx.x;
    if (i >= n4) return;
    float4 v = ((const float4*)in)[i];
    uint32_t h0 = packf16(v.x, v.y), h1 = packf16(v.z, v.w);
    float2 f0 = unpackf16(h0), f1 = unpackf16(h1);
    uint32_t l0 = packf16(v.x - f0.x, v.y - f0.y);
    uint32_t l1 = packf16(v.z - f1.x, v.w - f1.y);
    ((uint32_t*)hi)[2 * i] = h0; ((uint32_t*)hi)[2 * i + 1] = h1;
    ((uint32_t*)lo)[2 * i] = l0; ((uint32_t*)lo)[2 * i + 1] = l1;
}

// W_out [K,N] fp32 -> T [N,K] fp16
__global__ void transpose_kernel(const float* __restrict__ W,
                                 __half* __restrict__ T, int K, int N) {
    __shared__ float tile[32][33];
    const int bx = blockIdx.x * 32, by = blockIdx.y * 32;
    const int tx = threadIdx.x, ty = threadIdx.y;
#pragma unroll
    for (int i = 0; i < 32; i += 8)
        tile[ty + i][tx] = W[(by + ty + i) * N + bx + tx];
    __syncthreads();
#pragma unroll
    for (int i = 0; i < 32; i += 8)
        T[(bx + ty + i) * K + by + tx] = __float2half(tile[tx][ty + i]);
}

// W_qkv [K=1024, N=3072] fp32 -> permuted transposed fp16:
//   col n: g=n/192, w=n%192; w<128 -> wqk row g*128+w ; else wv row g*64+w-128
__global__ void transpose_permute_kernel(const float* __restrict__ W,
                                         __half* __restrict__ Tqk,
                                         __half* __restrict__ Tv, int K, int N) {
    __shared__ float tile[32][33];
    const int bx = blockIdx.x * 32, by = blockIdx.y * 32;
    const int tx = threadIdx.x, ty = threadIdx.y;
#pragma unroll
    for (int i = 0; i < 32; i += 8)
        tile[ty + i][tx] = W[(by + ty + i) * N + bx + tx];
    __syncthreads();
#pragma unroll
    for (int i = 0; i < 32; i += 8) {
        const int n = bx + ty + i;
        const int g = n / 192, w = n % 192;
        __half hv = __float2half(tile[tx][ty + i]);
        if (w < 128) Tqk[(ull)(g * 128 + w) * K + by + tx] = hv;
        else         Tv[(ull)(g * 64 + (w - 128)) * K + by + tx] = hv;
    }
}

__global__ void bias_permute_kernel(const float* __restrict__ b,
                                    float* __restrict__ bqk, float* __restrict__ bv) {
    int n = blockIdx.x * blockDim.x + threadIdx.x;
    if (n >= H3) return;
    const int g = n / 192, w = n % 192;
    if (w < 128) bqk[g * 128 + w] = b[n];
    else         bv[g * 64 + (w - 128)] = b[n];
}

// ----------------------------------------------------------------------------
// fp16 HMMA GEMM: C = Ah@B^T (+ Al@B^T if npass==2) + bias
// 128x128x32 tile, 256 threads, XOR-swizzled SMEM [Ah|Al|B], cp.async 2-buffer.
// ----------------------------------------------------------------------------
#define GBM 128
#define GBN 128
#define GBK 32
#define MATB 8192
#define BUFB (3 * MATB)
#define GSMEM (2 * BUFB)    // 48 KB

__global__ __launch_bounds__(256, 2)
void gemm_tc_kernel(const __half* __restrict__ Ah, const __half* __restrict__ Al,
                    const __half* __restrict__ Bw,
                    const float* __restrict__ bias, float* __restrict__ C,
                    __half* __restrict__ Ch, int npass, int M, int N, int K)
{
    extern __shared__ __align__(16) char gsm[];
    const uint32_t sb = s2u(gsm);
    const int t = threadIdx.x, lane = t & 31, warp = t >> 5;
    const int wm = warp & 1, wn = warp >> 1;
    const int bm = blockIdx.y * GBM, bn = blockIdx.x * GBN;
    const bool doAl = (npass == 2);

    const int srow = t >> 2;
    const int squad = t & 3;
    const uint32_t sq = (uint32_t)(squad ^ ((srow >> 1) & 3));
    const __half* a0 = Ah + (ull)(bm + srow) * K + squad * 8;
    const __half* b0 = Bw + (ull)(bn + srow) * K + squad * 8;
    const long dal = (long)(Al - Ah);
    const uint32_t sdst = sb + (uint32_t)srow * 64 + sq * 16;

    auto stage = [&](int kt, int buf) {
        const uint32_t d0 = sdst + (uint32_t)buf * BUFB;
        const __half* ap = a0 + kt * GBK;
        const __half* bp = b0 + kt * GBK;
        cp16(d0,                      ap);
        cp16(d0 + 4096,               ap + (ull)64 * K);
        if (doAl) {
            cp16(d0 + MATB,           ap + dal);
            cp16(d0 + MATB + 4096,    ap + dal + (ull)64 * K);
        }
        cp16(d0 + 2 * MATB,           bp);
        cp16(d0 + 2 * MATB + 4096,    bp + (ull)64 * K);
    };

    const int rA = wm * 64 + (lane & 15);
    const uint32_t fA = (uint32_t)((rA >> 1) & 3);
    const int hA = lane >> 4;
    const int rB = wn * 32 + (lane & 7) + (lane >> 4) * 8;
    const uint32_t fB = (uint32_t)((rB >> 1) & 3);
    const int hB = (lane >> 3) & 1;

    float acc[4][4][4];
#pragma unroll
    for (int mi = 0; mi < 4; mi++)
#pragma unroll
        for (int ni = 0; ni < 4; ni++)
#pragma unroll
            for (int j = 0; j < 4; j++) acc[mi][ni][j] = 0.0f;

    stage(0, 0); cp_commit();
    const int nkt = K / GBK;

    for (int kt = 0; kt < nkt; kt++) {
        const int cur = kt & 1;
        if (kt + 1 < nkt) { stage(kt + 1, cur ^ 1); cp_commit(); cp_wait<1>(); }
        else cp_wait<0>();
        __syncthreads();

        const uint32_t bb = sb + (uint32_t)cur * BUFB;
#pragma unroll
        for (int ks = 0; ks < 2; ks++) {
            uint32_t bh[2][4];
            const uint32_t qa = (((uint32_t)(2 * ks + hA)) ^ fA) * 16;
            const uint32_t qb = (((uint32_t)(2 * ks + hB)) ^ fB) * 16;
            const uint32_t arow = bb + (uint32_t)rA * 64 + qa;
            const uint32_t brow = bb + 2 * MATB + (uint32_t)rB * 64 + qb;
#pragma unroll
            for (int np = 0; np < 2; np++)
                ldm_x4(bh[np], brow + np * 1024);
#pragma unroll
            for (int mi = 0; mi < 4; mi++) {
                uint32_t ah[4];
                ldm_x4(ah, arow + mi * 1024);
#pragma unroll
                for (int ni = 0; ni < 4; ni++)
                    mma16(acc[mi][ni], ah, &bh[ni >> 1][(ni & 1) * 2]);
                if (doAl) {
                    uint32_t al[4];
                    ldm_x4(al, arow + MATB + mi * 1024);
#pragma unroll
                    for (int ni = 0; ni < 4; ni++)
                        mma16(acc[mi][ni], al, &bh[ni >> 1][(ni & 1) * 2]);
                }
            }
        }
        __syncthreads();
    }

    // epilogue
    const int rbase = bm + wm * 64 + (lane >> 2);
    const int cbase = bn + wn * 32 + (lane & 3) * 2;
#pragma unroll
    for (int mi = 0; mi < 4; mi++) {
#pragma unroll
        for (int ni = 0; ni < 4; ni++) {
            const int col = cbase + ni * 8;
            const float bz0 = bias[col], bz1 = bias[col + 1];
            const int r0 = rbase + mi * 16;
            float o00 = acc[mi][ni][0] + bz0, o01 = acc[mi][ni][1] + bz1;
            float o10 = acc[mi][ni][2] + bz0, o11 = acc[mi][ni][3] + bz1;
            if (Ch) {
                *(uint32_t*)(Ch + (ull)r0 * N + col)       = packf16(o00, o01);
                *(uint32_t*)(Ch + (ull)(r0 + 8) * N + col) = packf16(o10, o11);
            } else {
                float2 ax; ax.x = o00; ax.y = o01;
                float2 ay; ay.x = o10; ay.y = o11;
                *(float2*)(C + (ull)r0 * N + col) = ax;
                *(float2*)(C + (ull)(r0 + 8) * N + col) = ay;
            }
        }
    }
}

// ----------------------------------------------------------------------------
// fp16 HMMA causal flash attention over the split qk/v buffers.
// QK 1-pass, PV 2-pass (P hi/lo, V fragments reused).
// ----------------------------------------------------------------------------
#define LQ 72
#define QS_ELEMS (128 * LQ)
#define MAT_ELEMS (64 * LQ)
#define ATTN_SMEM ((QS_ELEMS + 2 * 2 * MAT_ELEMS) * 2)

__global__ __launch_bounds__(256)
void attn_kernel()
{
    extern __shared__ __align__(16) __half sm[];
    __half* Qs = sm;
    __half* KV = sm + QS_ELEMS;   // [buf][2][64*LQ]  (K, V)

    const int t = threadIdx.x, lane = t & 31, w = t >> 5;
    const int qi = 15 - (int)blockIdx.x;
    const int bh = blockIdx.y, b = bh >> 4, h = bh & 15;
    const __half* Gqk = g_qk + (ull)b * (S_ * 2048) + (ull)h * (S_ * 128);
    const __half* Gv  = g_v  + (ull)b * (S_ * 1024) + (ull)h * (S_ * 64);
    const int qbase = qi * 128;

#pragma unroll
    for (int i = t; i < 128 * 8; i += 256) {
        int row = i >> 3, seg = i & 7;
        *(uint4*)(Qs + row * LQ + seg * 8) =
            *(const uint4*)(Gqk + (ull)(qbase + row) * 128 + seg * 8);
    }

    const uint32_t kvB = s2u(KV);
    auto stage = [&](int kt, int buf) {
        const int j0 = kt * 64;
        const uint32_t dstb = kvB + buf * (2 * MAT_ELEMS * 2);
#pragma unroll
        for (int i = t; i < 2 * 64 * 8; i += 256) {
            int mmat = i >> 9;            // 0 = K, 1 = V
            int row = (i >> 3) & 63;
            int seg = i & 7;
            const __half* src = mmat
                ? Gv  + (ull)(j0 + row) * 64 + seg * 8
                : Gqk + (ull)(j0 + row) * 128 + 64 + seg * 8;
            cp16(dstb + (mmat * MAT_ELEMS + row * LQ + seg * 8) * 2, src);
        }
    };

    stage(0, 0); cp_commit();

    const int nkt = 2 * (qi + 1);
    const int r0g = qbase + w * 16 + (lane >> 2);
    const int r1g = r0g + 8;
    const float scale = 0.02209708691f;   // (2*1024)^-0.5

    float m0 = -1e30f, m1 = -1e30f, l0 = 0.0f, l1 = 0.0f;
    float co[8][4];
#pragma unroll
    for (int i = 0; i < 8; i++)
#pragma unroll
        for (int j = 0; j < 4; j++) co[i][j] = 0.0f;

    uint32_t qf[4][4];
    bool qloaded = false;
    const uint32_t qaddr0 = s2u(Qs) + ((uint32_t)(w * 16 + (lane & 15)) * LQ + (lane >> 4) * 8) * 2;

    for (int kt = 0; kt < nkt; kt++) {
        const int cur = kt & 1;
        if (kt + 1 < nkt) { stage(kt + 1, cur ^ 1); cp_commit(); cp_wait<1>(); }
        else cp_wait<0>();
        __syncthreads();

        if (!qloaded) {
#pragma unroll
            for (int ks = 0; ks < 4; ks++) ldm_x4(qf[ks], qaddr0 + ks * 32);
            qloaded = true;
        }

        const uint32_t bufb = kvB + cur * (2 * MAT_ELEMS * 2);
        const uint32_t KhB = bufb, VhB = bufb + MAT_ELEMS * 2;

        // ---- S = Q @ K^T ----
        float cs[8][4];
#pragma unroll
        for (int i = 0; i < 8; i++)
#pragma unroll
            for (int j = 0; j < 4; j++) cs[i][j] = 0.0f;

        const uint32_t kfoff = ((uint32_t)((lane & 7) + ((lane >> 4) & 1) * 8) * LQ
                                + ((lane >> 3) & 1) * 8) * 2;
#pragma unroll
        for (int ks = 0; ks < 4; ks++) {
#pragma unroll
            for (int nip = 0; nip < 4; nip++) {
                uint32_t bfr[4];
                ldm_x4(bfr, KhB + kfoff + ((uint32_t)nip * 16 * LQ + ks * 16) * 2);
                mma16(cs[2 * nip],     qf[ks], bfr);
                mma16(cs[2 * nip + 1], qf[ks], bfr + 2);
            }
        }

        // ---- mask + scale + online softmax ----
        const int cb = kt * 64 + 2 * (lane & 3);
        float sv0[16], sv1[16];
        float tm0 = -1e30f, tm1 = -1e30f;
#pragma unroll
        for (int ni = 0; ni < 8; ni++) {
#pragma unroll
            for (int e = 0; e < 2; e++) {
                const int col = cb + ni * 8 + e;
                float v0 = (col <= r0g) ? cs[ni][e]     * scale : -1e30f;
                float v1 = (col <= r1g) ? cs[ni][2 + e] * scale : -1e30f;
                sv0[ni * 2 + e] = v0; sv1[ni * 2 + e] = v1;
                tm0 = fmaxf(tm0, v0); tm1 = fmaxf(tm1, v1);
            }
        }
        tm0 = fmaxf(tm0, __shfl_xor_sync(0xffffffffu, tm0, 1));
        tm0 = fmaxf(tm0, __shfl_xor_sync(0xffffffffu, tm0, 2));
        tm1 = fmaxf(tm1, __shfl_xor_sync(0xffffffffu, tm1, 1));
        tm1 = fmaxf(tm1, __shfl_xor_sync(0xffffffffu, tm1, 2));
        const float mn0 = fmaxf(m0, tm0), mn1 = fmaxf(m1, tm1);
        const float corr0 = __expf(m0 - mn0), corr1 = __expf(m1 - mn1);
        m0 = mn0; m1 = mn1;
        float ps0 = 0.0f, ps1 = 0.0f;
#pragma unroll
        for (int i = 0; i < 16; i++) {
            sv0[i] = __expf(sv0[i] - mn0); ps0 += sv0[i];
            sv1[i] = __expf(sv1[i] - mn1); ps1 += sv1[i];
        }
        ps0 += __shfl_xor_sync(0xffffffffu, ps0, 1);
        ps0 += __shfl_xor_sync(0xffffffffu, ps0, 2);
        ps1 += __shfl_xor_sync(0xffffffffu, ps1, 1);
        ps1 += __shfl_xor_sync(0xffffffffu, ps1, 2);
        l0 = l0 * corr0 + ps0;
        l1 = l1 * corr1 + ps1;
#pragma unroll
        for (int nd = 0; nd < 8; nd++) {
            co[nd][0] *= corr0; co[nd][1] *= corr0;
            co[nd][2] *= corr1; co[nd][3] *= corr1;
        }

        // ---- P hi/lo fp16 A-fragments straight from S fragments ----
        uint32_t ph[4][4], pl[4][4];
#pragma unroll
        for (int kj = 0; kj < 4; kj++) {
            uint32_t a0 = packf16(sv0[4 * kj],     sv0[4 * kj + 1]);
            uint32_t a1 = packf16(sv1[4 * kj],     sv1[4 * kj + 1]);
            uint32_t a2 = packf16(sv0[4 * kj + 2], sv0[4 * kj + 3]);
            uint32_t a3 = packf16(sv1[4 * kj + 2], sv1[4 * kj + 3]);
            ph[kj][0] = a0; ph[kj][1] = a1; ph[kj][2] = a2; ph[kj][3] = a3;
            float2 f0 = unpackf16(a0), f1 = unpackf16(a1);
            float2 f2 = unpackf16(a2), f3 = unpackf16(a3);
            pl[kj][0] = packf16(sv0[4 * kj] - f0.x,     sv0[4 * kj + 1] - f0.y);
            pl[kj][1] = packf16(sv1[4 * kj] - f1.x,     sv1[4 * kj + 1] - f1.y);
            pl[kj][2] = packf16(sv0[4 * kj + 2] - f2.x, sv0[4 * kj + 3] - f2.y);
            pl[kj][3] = packf16(sv1[4 * kj + 2] - f3.x, sv1[4 * kj + 3] - f3.y);
        }

        // ---- O += (Ph + Pl) @ V ----
        const uint32_t vfoff = ((uint32_t)(lane & 15) * LQ) * 2 + (lane >> 4) * 16;
#pragma unroll
        for (int kj = 0; kj < 4; kj++) {
#pragma unroll
            for (int ndp = 0; ndp < 4; ndp++) {
                uint32_t bfr[4];
                ldm_x4_t(bfr, VhB + vfoff + (uint32_t)kj * 16 * LQ * 2 + ndp * 32);
                mma16(co[2 * ndp],     ph[kj], bfr);
                mma16(co[2 * ndp + 1], ph[kj], bfr + 2);
                mma16(co[2 * ndp],     pl[kj], bfr);
                mma16(co[2 * ndp + 1], pl[kj], bfr + 2);
            }
        }
        __syncthreads();
    }

    // ---- normalize, split hi/lo fp16, store to scrambled sa layout ----
    const float il0 = 1.0f / l0, il1 = 1.0f / l1;
    const ull row0 = (ull)(b * S_ + h * 128 + (r0g >> 4)) * E_ + (r0g & 15) * 64;
    const ull row1 = (ull)(b * S_ + h * 128 + (r1g >> 4)) * E_ + (r1g & 15) * 64;
    const int dcol = 2 * (lane & 3);
#pragma unroll
    for (int nd = 0; nd < 8; nd++) {
        const int d = nd * 8 + dcol;
        float o00 = co[nd][0] * il0, o01 = co[nd][1] * il0;
        float o10 = co[nd][2] * il1, o11 = co[nd][3] * il1;
        uint32_t h0 = packf16(o00, o01);
        uint32_t h1 = packf16(o10, o11);
        float2 f0 = unpackf16(h0), f1 = unpackf16(h1);
        uint32_t q0 = packf16(o00 - f0.x, o01 - f0.y);
        uint32_t q1 = packf16(o10 - f1.x, o11 - f1.y);
        *(uint32_t*)(g_sah + row0 + d) = h0;
        *(uint32_t*)(g_sah + row1 + d) = h1;
        *(uint32_t*)(g_sal + row0 + d) = q0;
        *(uint32_t*)(g_sal + row1 + d) = q1;
    }
}

// ----------------------------------------------------------------------------
extern "C" void kernel_launch(void* const* d_in, const int* in_sizes, int n_in,
                              void* d_out, int out_size)
{
    const float* x     = (const float*)d_in[0];
    const float* W_qkv = (const float*)d_in[1];
    const float* b_qkv = (const float*)d_in[2];
    const float* W_out = (const float*)d_in[3];
    const float* b_out = (const float*)d_in[4];
    float* out = (float*)d_out;

    __half *qk, *v, *xh, *xl, *wqk, *wv, *wo, *sah, *sal;
    float *bqk, *bv;
    cudaGetSymbolAddress((void**)&qk, g_qk);   cudaGetSymbolAddress((void**)&v, g_v);
    cudaGetSymbolAddress((void**)&xh, g_xh);   cudaGetSymbolAddress((void**)&xl, g_xl);
    cudaGetSymbolAddress((void**)&wqk, g_wqk); cudaGetSymbolAddress((void**)&wv, g_wv);
    cudaGetSymbolAddress((void**)&wo, g_wo);
    cudaGetSymbolAddress((void**)&bqk, g_bqk); cudaGetSymbolAddress((void**)&bv, g_bv);
    cudaGetSymbolAddress((void**)&sah, g_sah); cudaGetSymbolAddress((void**)&sal, g_sal);

    cudaFuncSetAttribute(attn_kernel,
                         cudaFuncAttributeMaxDynamicSharedMemorySize, ATTN_SMEM);
    cudaFuncSetAttribute(gemm_tc_kernel,
                         cudaFuncAttributeMaxDynamicSharedMemorySize, GSMEM);

    // 0) operand prep
    {
        const int n4 = MROWS * E_ / 4;
        split_kernel<<<(n4 + 255) / 256, 256>>>(x, xh, xl, n4);
        transpose_permute_kernel<<<dim3(H3 / 32, E_ / 32), dim3(32, 8)>>>(
            W_qkv, wqk, wv, E_, H3);
        transpose_kernel<<<dim3(E_ / 32, E_ / 32), dim3(32, 8)>>>(W_out, wo, E_, E_);
        bias_permute_kernel<<<(H3 + 255) / 256, 256>>>(b_qkv, bqk, bv);
    }

    // 1a) q,k projection (1-pass) -> g_qk [8192, 2048]
    gemm_tc_kernel<<<dim3(2048 / GBN, MROWS / GBM), 256, GSMEM>>>(
        xh, xl, wqk, bqk, nullptr, qk, /*npass=*/1, MROWS, 2048, E_);

    // 1b) v projection (2-pass) -> g_v [8192, 1024]
    gemm_tc_kernel<<<dim3(1024 / GBN, MROWS / GBM), 256, GSMEM>>>(
        xh, xl, wv, bv, nullptr, v, /*npass=*/2, MROWS, 1024, E_);

    // 2) fp16 HMMA causal attention -> hi/lo fp16 sa
    attn_kernel<<<dim3(16, B_ * NH), 256, ATTN_SMEM>>>();

    // 3) output projection (2-pass) -> fp32 out
    gemm_tc_kernel<<<dim3(E_ / GBN, MROWS / GBM), 256, GSMEM>>>(
        sah, sal, wo, b_out, out, nullptr, /*npass=*/2, MROWS, E_, E_);
}

// round 17
// speedup vs baseline: 1.7504x; 1.1338x over previous
#include <cuda_runtime.h>
#include <cuda_fp16.h>
#include <cstdint>

// ----------------------------------------------------------------------------
// MaskedMSA: x@Wqkv+b -> (faithful reshape) -> causal MHA -> sa@Wout+b
// B=4, S=2048, E=1024, HIDDEN=1024, HEADS=16, d_head=64
// fp16 HMMA. qkv in COLUMN-PERMUTED split buffers:
//   g_qk [8192, 2048]  (q,k; 1-pass GEMM — softmax attenuates error)
//   g_v  [8192, 1024]  (v; 2-pass GEMM — linear path)
// Attention: QK 1-pass, PV 1-pass (P fp16; linear-path eps 2.4e-4).
// GEMM3: 1-pass on fp16 sa. Total error budget ~5e-4 vs 1e-3 gate.
// ----------------------------------------------------------------------------

#define B_  4
#define S_  2048
#define E_  1024
#define H3  3072
#define NH  16
#define MROWS (B_ * S_)   // 8192

typedef unsigned long long ull;

// ---------------- scratch (no cudaMalloc allowed) ----------------
__device__ __half g_qk[MROWS * 2048];    // permuted q,k  (head h: block S*128)
__device__ __half g_v [MROWS * 1024];    // permuted v    (head h: block S*64)
__device__ __half g_xh[MROWS * E_];      // x hi/lo fp16
__device__ __half g_xl[MROWS * E_];
__device__ __half g_wqk[2048 * E_];      // permuted W_qkv^T (qk rows)
__device__ __half g_wv [1024 * E_];      // permuted W_qkv^T (v rows)
__device__ __half g_wo[E_ * E_];         // W_out^T fp16
__device__ float  g_bqk[2048];           // permuted bias
__device__ float  g_bv [1024];
__device__ __half g_sa[MROWS * E_];      // attention out, single fp16

// ---------------- helpers ----------------
__device__ __forceinline__ uint32_t s2u(const void* p) {
    uint32_t a;
    asm("{ .reg .u64 t; cvta.to.shared.u64 t, %1; cvt.u32.u64 %0, t; }" : "=r"(a) : "l"(p));
    return a;
}
__device__ __forceinline__ void ldm_x4(uint32_t* r, uint32_t addr) {
    asm volatile("ldmatrix.sync.aligned.m8n8.x4.shared.b16 {%0,%1,%2,%3}, [%4];"
                 : "=r"(r[0]), "=r"(r[1]), "=r"(r[2]), "=r"(r[3]) : "r"(addr));
}
__device__ __forceinline__ void ldm_x4_t(uint32_t* r, uint32_t addr) {
    asm volatile("ldmatrix.sync.aligned.m8n8.x4.trans.shared.b16 {%0,%1,%2,%3}, [%4];"
                 : "=r"(r[0]), "=r"(r[1]), "=r"(r[2]), "=r"(r[3]) : "r"(addr));
}
__device__ __forceinline__ void mma16(float* d, const uint32_t* a, const uint32_t* b) {
    asm volatile("mma.sync.aligned.m16n8k16.row.col.f32.f16.f16.f32 "
                 "{%0,%1,%2,%3}, {%4,%5,%6,%7}, {%8,%9}, {%0,%1,%2,%3};"
                 : "+f"(d[0]), "+f"(d[1]), "+f"(d[2]), "+f"(d[3])
                 : "r"(a[0]), "r"(a[1]), "r"(a[2]), "r"(a[3]), "r"(b[0]), "r"(b[1]));
}
__device__ __forceinline__ uint32_t packf16(float lo, float hi) {
    uint32_t r; asm("cvt.rn.f16x2.f32 %0, %1, %2;" : "=r"(r) : "f"(hi), "f"(lo)); return r;
}
__device__ __forceinline__ float2 unpackf16(uint32_t v) {
    __half2 h = *reinterpret_cast<__half2*>(&v);
    return __half22float2(h);
}
__device__ __forceinline__ void cp16(uint32_t dst, const void* src) {
    asm volatile("cp.async.ca.shared.global [%0], [%1], 16;" :: "r"(dst), "l"(src));
}
__device__ __forceinline__ void cp_commit() { asm volatile("cp.async.commit_group;" ::: "memory"); }
template <int N> __device__ __forceinline__ void cp_wait() {
    asm volatile("cp.async.wait_group %0;" :: "n"(N) : "memory");
}

// ----------------------------------------------------------------------------
// Prep kernels
// ----------------------------------------------------------------------------
__global__ void split_kernel(const float* __restrict__ in,
                             __half* __restrict__ hi, __half* __restrict__ lo, int n4) {
    int i = blockIdx.x * blockDim.x + threadIdx.x;
    if (i >= n4) return;
    float4 v = ((const float4*)in)[i];
    uint32_t h0 = packf16(v.x, v.y), h1 = packf16(v.z, v.w);
    float2 f0 = unpackf16(h0), f1 = unpackf16(h1);
    uint32_t l0 = packf16(v.x - f0.x, v.y - f0.y);
    uint32_t l1 = packf16(v.z - f1.x, v.w - f1.y);
    ((uint32_t*)hi)[2 * i] = h0; ((uint32_t*)hi)[2 * i + 1] = h1;
    ((uint32_t*)lo)[2 * i] = l0; ((uint32_t*)lo)[2 * i + 1] = l1;
}

// W_out [K,N] fp32 -> T [N,K] fp16
__global__ void transpose_kernel(const float* __restrict__ W,
                                 __half* __restrict__ T, int K, int N) {
    __shared__ float tile[32][33];
    const int bx = blockIdx.x * 32, by = blockIdx.y * 32;
    const int tx = threadIdx.x, ty = threadIdx.y;
#pragma unroll
    for (int i = 0; i < 32; i += 8)
        tile[ty + i][tx] = W[(by + ty + i) * N + bx + tx];
    __syncthreads();
#pragma unroll
    for (int i = 0; i < 32; i += 8)
        T[(bx + ty + i) * K + by + tx] = __float2half(tile[tx][ty + i]);
}

// W_qkv [K=1024, N=3072] fp32 -> permuted transposed fp16:
//   col n: g=n/192, w=n%192; w<128 -> wqk row g*128+w ; else wv row g*64+w-128
__global__ void transpose_permute_kernel(const float* __restrict__ W,
                                         __half* __restrict__ Tqk,
                                         __half* __restrict__ Tv, int K, int N) {
    __shared__ float tile[32][33];
    const int bx = blockIdx.x * 32, by = blockIdx.y * 32;
    const int tx = threadIdx.x, ty = threadIdx.y;
#pragma unroll
    for (int i = 0; i < 32; i += 8)
        tile[ty + i][tx] = W[(by + ty + i) * N + bx + tx];
    __syncthreads();
#pragma unroll
    for (int i = 0; i < 32; i += 8) {
        const int n = bx + ty + i;
        const int g = n / 192, w = n % 192;
        __half hv = __float2half(tile[tx][ty + i]);
        if (w < 128) Tqk[(ull)(g * 128 + w) * K + by + tx] = hv;
        else         Tv[(ull)(g * 64 + (w - 128)) * K + by + tx] = hv;
    }
}

__global__ void bias_permute_kernel(const float* __restrict__ b,
                                    float* __restrict__ bqk, float* __restrict__ bv) {
    int n = blockIdx.x * blockDim.x + threadIdx.x;
    if (n >= H3) return;
    const int g = n / 192, w = n % 192;
    if (w < 128) bqk[g * 128 + w] = b[n];
    else         bv[g * 64 + (w - 128)] = b[n];
}

// ----------------------------------------------------------------------------
// fp16 HMMA GEMM: C = Ah@B^T (+ Al@B^T if npass==2) + bias
// 128x128x32 tile, 256 threads, XOR-swizzled SMEM [Ah|Al|B], cp.async 2-buffer.
// ----------------------------------------------------------------------------
#define GBM 128
#define GBN 128
#define GBK 32
#define MATB 8192
#define BUFB (3 * MATB)
#define GSMEM (2 * BUFB)    // 48 KB

__global__ __launch_bounds__(256, 2)
void gemm_tc_kernel(const __half* __restrict__ Ah, const __half* __restrict__ Al,
                    const __half* __restrict__ Bw,
                    const float* __restrict__ bias, float* __restrict__ C,
                    __half* __restrict__ Ch, int npass, int M, int N, int K)
{
    extern __shared__ __align__(16) char gsm[];
    const uint32_t sb = s2u(gsm);
    const int t = threadIdx.x, lane = t & 31, warp = t >> 5;
    const int wm = warp & 1, wn = warp >> 1;
    const int bm = blockIdx.y * GBM, bn = blockIdx.x * GBN;
    const bool doAl = (npass == 2);

    const int srow = t >> 2;
    const int squad = t & 3;
    const uint32_t sq = (uint32_t)(squad ^ ((srow >> 1) & 3));
    const __half* a0 = Ah + (ull)(bm + srow) * K + squad * 8;
    const __half* b0 = Bw + (ull)(bn + srow) * K + squad * 8;
    const long dal = (long)(Al - Ah);
    const uint32_t sdst = sb + (uint32_t)srow * 64 + sq * 16;

    auto stage = [&](int kt, int buf) {
        const uint32_t d0 = sdst + (uint32_t)buf * BUFB;
        const __half* ap = a0 + kt * GBK;
        const __half* bp = b0 + kt * GBK;
        cp16(d0,                      ap);
        cp16(d0 + 4096,               ap + (ull)64 * K);
        if (doAl) {
            cp16(d0 + MATB,           ap + dal);
            cp16(d0 + MATB + 4096,    ap + dal + (ull)64 * K);
        }
        cp16(d0 + 2 * MATB,           bp);
        cp16(d0 + 2 * MATB + 4096,    bp + (ull)64 * K);
    };

    const int rA = wm * 64 + (lane & 15);
    const uint32_t fA = (uint32_t)((rA >> 1) & 3);
    const int hA = lane >> 4;
    const int rB = wn * 32 + (lane & 7) + (lane >> 4) * 8;
    const uint32_t fB = (uint32_t)((rB >> 1) & 3);
    const int hB = (lane >> 3) & 1;

    float acc[4][4][4];
#pragma unroll
    for (int mi = 0; mi < 4; mi++)
#pragma unroll
        for (int ni = 0; ni < 4; ni++)
#pragma unroll
            for (int j = 0; j < 4; j++) acc[mi][ni][j] = 0.0f;

    stage(0, 0); cp_commit();
    const int nkt = K / GBK;

    for (int kt = 0; kt < nkt; kt++) {
        const int cur = kt & 1;
        if (kt + 1 < nkt) { stage(kt + 1, cur ^ 1); cp_commit(); cp_wait<1>(); }
        else cp_wait<0>();
        __syncthreads();

        const uint32_t bb = sb + (uint32_t)cur * BUFB;
#pragma unroll
        for (int ks = 0; ks < 2; ks++) {
            uint32_t bh[2][4];
            const uint32_t qa = (((uint32_t)(2 * ks + hA)) ^ fA) * 16;
            const uint32_t qb = (((uint32_t)(2 * ks + hB)) ^ fB) * 16;
            const uint32_t arow = bb + (uint32_t)rA * 64 + qa;
            const uint32_t brow = bb + 2 * MATB + (uint32_t)rB * 64 + qb;
#pragma unroll
            for (int np = 0; np < 2; np++)
                ldm_x4(bh[np], brow + np * 1024);
#pragma unroll
            for (int mi = 0; mi < 4; mi++) {
                uint32_t ah[4];
                ldm_x4(ah, arow + mi * 1024);
#pragma unroll
                for (int ni = 0; ni < 4; ni++)
                    mma16(acc[mi][ni], ah, &bh[ni >> 1][(ni & 1) * 2]);
                if (doAl) {
                    uint32_t al[4];
                    ldm_x4(al, arow + MATB + mi * 1024);
#pragma unroll
                    for (int ni = 0; ni < 4; ni++)
                        mma16(acc[mi][ni], al, &bh[ni >> 1][(ni & 1) * 2]);
                }
            }
        }
        __syncthreads();
    }

    // epilogue
    const int rbase = bm + wm * 64 + (lane >> 2);
    const int cbase = bn + wn * 32 + (lane & 3) * 2;
#pragma unroll
    for (int mi = 0; mi < 4; mi++) {
#pragma unroll
        for (int ni = 0; ni < 4; ni++) {
            const int col = cbase + ni * 8;
            const float bz0 = bias[col], bz1 = bias[col + 1];
            const int r0 = rbase + mi * 16;
            float o00 = acc[mi][ni][0] + bz0, o01 = acc[mi][ni][1] + bz1;
            float o10 = acc[mi][ni][2] + bz0, o11 = acc[mi][ni][3] + bz1;
            if (Ch) {
                *(uint32_t*)(Ch + (ull)r0 * N + col)       = packf16(o00, o01);
                *(uint32_t*)(Ch + (ull)(r0 + 8) * N + col) = packf16(o10, o11);
            } else {
                float2 ax; ax.x = o00; ax.y = o01;
                float2 ay; ay.x = o10; ay.y = o11;
                *(float2*)(C + (ull)r0 * N + col) = ax;
                *(float2*)(C + (ull)(r0 + 8) * N + col) = ay;
            }
        }
    }
}

// ----------------------------------------------------------------------------
// fp16 HMMA causal flash attention over the split qk/v buffers.
// QK 1-pass, PV 1-pass (P fp16). Writes single fp16 sa.
// ----------------------------------------------------------------------------
#define LQ 72
#define QS_ELEMS (128 * LQ)
#define MAT_ELEMS (64 * LQ)
#define ATTN_SMEM ((QS_ELEMS + 2 * 2 * MAT_ELEMS) * 2)

__global__ __launch_bounds__(256)
void attn_kernel()
{
    extern __shared__ __align__(16) __half sm[];
    __half* Qs = sm;
    __half* KV = sm + QS_ELEMS;   // [buf][2][64*LQ]  (K, V)

    const int t = threadIdx.x, lane = t & 31, w = t >> 5;
    const int qi = 15 - (int)blockIdx.x;
    const int bh = blockIdx.y, b = bh >> 4, h = bh & 15;
    const __half* Gqk = g_qk + (ull)b * (S_ * 2048) + (ull)h * (S_ * 128);
    const __half* Gv  = g_v  + (ull)b * (S_ * 1024) + (ull)h * (S_ * 64);
    const int qbase = qi * 128;

#pragma unroll
    for (int i = t; i < 128 * 8; i += 256) {
        int row = i >> 3, seg = i & 7;
        *(uint4*)(Qs + row * LQ + seg * 8) =
            *(const uint4*)(Gqk + (ull)(qbase + row) * 128 + seg * 8);
    }

    const uint32_t kvB = s2u(KV);
    auto stage = [&](int kt, int buf) {
        const int j0 = kt * 64;
        const uint32_t dstb = kvB + buf * (2 * MAT_ELEMS * 2);
#pragma unroll
        for (int i = t; i < 2 * 64 * 8; i += 256) {
            int mmat = i >> 9;            // 0 = K, 1 = V
            int row = (i >> 3) & 63;
            int seg = i & 7;
            const __half* src = mmat
                ? Gv  + (ull)(j0 + row) * 64 + seg * 8
                : Gqk + (ull)(j0 + row) * 128 + 64 + seg * 8;
            cp16(dstb + (mmat * MAT_ELEMS + row * LQ + seg * 8) * 2, src);
        }
    };

    stage(0, 0); cp_commit();

    const int nkt = 2 * (qi + 1);
    const int r0g = qbase + w * 16 + (lane >> 2);
    const int r1g = r0g + 8;
    const float scale = 0.02209708691f;   // (2*1024)^-0.5

    float m0 = -1e30f, m1 = -1e30f, l0 = 0.0f, l1 = 0.0f;
    float co[8][4];
#pragma unroll
    for (int i = 0; i < 8; i++)
#pragma unroll
        for (int j = 0; j < 4; j++) co[i][j] = 0.0f;

    uint32_t qf[4][4];
    bool qloaded = false;
    const uint32_t qaddr0 = s2u(Qs) + ((uint32_t)(w * 16 + (lane & 15)) * LQ + (lane >> 4) * 8) * 2;

    for (int kt = 0; kt < nkt; kt++) {
        const int cur = kt & 1;
        if (kt + 1 < nkt) { stage(kt + 1, cur ^ 1); cp_commit(); cp_wait<1>(); }
        else cp_wait<0>();
        __syncthreads();

        if (!qloaded) {
#pragma unroll
            for (int ks = 0; ks < 4; ks++) ldm_x4(qf[ks], qaddr0 + ks * 32);
            qloaded = true;
        }

        const uint32_t bufb = kvB + cur * (2 * MAT_ELEMS * 2);
        const uint32_t KhB = bufb, VhB = bufb + MAT_ELEMS * 2;

        // ---- S = Q @ K^T ----
        float cs[8][4];
#pragma unroll
        for (int i = 0; i < 8; i++)
#pragma unroll
            for (int j = 0; j < 4; j++) cs[i][j] = 0.0f;

        const uint32_t kfoff = ((uint32_t)((lane & 7) + ((lane >> 4) & 1) * 8) * LQ
                                + ((lane >> 3) & 1) * 8) * 2;
#pragma unroll
        for (int ks = 0; ks < 4; ks++) {
#pragma unroll
            for (int nip = 0; nip < 4; nip++) {
                uint32_t bfr[4];
                ldm_x4(bfr, KhB + kfoff + ((uint32_t)nip * 16 * LQ + ks * 16) * 2);
                mma16(cs[2 * nip],     qf[ks], bfr);
                mma16(cs[2 * nip + 1], qf[ks], bfr + 2);
            }
        }

        // ---- mask + scale + online softmax ----
        const int cb = kt * 64 + 2 * (lane & 3);
        float sv0[16], sv1[16];
        float tm0 = -1e30f, tm1 = -1e30f;
#pragma unroll
        for (int ni = 0; ni < 8; ni++) {
#pragma unroll
            for (int e = 0; e < 2; e++) {
                const int col = cb + ni * 8 + e;
                float v0 = (col <= r0g) ? cs[ni][e]     * scale : -1e30f;
                float v1 = (col <= r1g) ? cs[ni][2 + e] * scale : -1e30f;
                sv0[ni * 2 + e] = v0; sv1[ni * 2 + e] = v1;
                tm0 = fmaxf(tm0, v0); tm1 = fmaxf(tm1, v1);
            }
        }
        tm0 = fmaxf(tm0, __shfl_xor_sync(0xffffffffu, tm0, 1));
        tm0 = fmaxf(tm0, __shfl_xor_sync(0xffffffffu, tm0, 2));
        tm1 = fmaxf(tm1, __shfl_xor_sync(0xffffffffu, tm1, 1));
        tm1 = fmaxf(tm1, __shfl_xor_sync(0xffffffffu, tm1, 2));
        const float mn0 = fmaxf(m0, tm0), mn1 = fmaxf(m1, tm1);
        const float corr0 = __expf(m0 - mn0), corr1 = __expf(m1 - mn1);
        m0 = mn0; m1 = mn1;
        float ps0 = 0.0f, ps1 = 0.0f;
#pragma unroll
        for (int i = 0; i < 16; i++) {
            sv0[i] = __expf(sv0[i] - mn0); ps0 += sv0[i];
            sv1[i] = __expf(sv1[i] - mn1); ps1 += sv1[i];
        }
        ps0 += __shfl_xor_sync(0xffffffffu, ps0, 1);
        ps0 += __shfl_xor_sync(0xffffffffu, ps0, 2);
        ps1 += __shfl_xor_sync(0xffffffffu, ps1, 1);
        ps1 += __shfl_xor_sync(0xffffffffu, ps1, 2);
        l0 = l0 * corr0 + ps0;
        l1 = l1 * corr1 + ps1;
#pragma unroll
        for (int nd = 0; nd < 8; nd++) {
            co[nd][0] *= corr0; co[nd][1] *= corr0;
            co[nd][2] *= corr1; co[nd][3] *= corr1;
        }

        // ---- P fp16 A-fragments straight from S fragments ----
        uint32_t ph[4][4];
#pragma unroll
        for (int kj = 0; kj < 4; kj++) {
            ph[kj][0] = packf16(sv0[4 * kj],     sv0[4 * kj + 1]);
            ph[kj][1] = packf16(sv1[4 * kj],     sv1[4 * kj + 1]);
            ph[kj][2] = packf16(sv0[4 * kj + 2], sv0[4 * kj + 3]);
            ph[kj][3] = packf16(sv1[4 * kj + 2], sv1[4 * kj + 3]);
        }

        // ---- O += P @ V ----
        const uint32_t vfoff = ((uint32_t)(lane & 15) * LQ) * 2 + (lane >> 4) * 16;
#pragma unroll
        for (int kj = 0; kj < 4; kj++) {
#pragma unroll
            for (int ndp = 0; ndp < 4; ndp++) {
                uint32_t bfr[4];
                ldm_x4_t(bfr, VhB + vfoff + (uint32_t)kj * 16 * LQ * 2 + ndp * 32);
                mma16(co[2 * ndp],     ph[kj], bfr);
                mma16(co[2 * ndp + 1], ph[kj], bfr + 2);
            }
        }
        __syncthreads();
    }

    // ---- normalize, store single fp16 to scrambled sa layout ----
    const float il0 = 1.0f / l0, il1 = 1.0f / l1;
    const ull row0 = (ull)(b * S_ + h * 128 + (r0g >> 4)) * E_ + (r0g & 15) * 64;
    const ull row1 = (ull)(b * S_ + h * 128 + (r1g >> 4)) * E_ + (r1g & 15) * 64;
    const int dcol = 2 * (lane & 3);
#pragma unroll
    for (int nd = 0; nd < 8; nd++) {
        const int d = nd * 8 + dcol;
        *(uint32_t*)(g_sa + row0 + d) = packf16(co[nd][0] * il0, co[nd][1] * il0);
        *(uint32_t*)(g_sa + row1 + d) = packf16(co[nd][2] * il1, co[nd][3] * il1);
    }
}

// ----------------------------------------------------------------------------
extern "C" void kernel_launch(void* const* d_in, const int* in_sizes, int n_in,
                              void* d_out, int out_size)
{
    const float* x     = (const float*)d_in[0];
    const float* W_qkv = (const float*)d_in[1];
    const float* b_qkv = (const float*)d_in[2];
    const float* W_out = (const float*)d_in[3];
    const float* b_out = (const float*)d_in[4];
    float* out = (float*)d_out;

    __half *qk, *v, *xh, *xl, *wqk, *wv, *wo, *sa;
    float *bqk, *bv;
    cudaGetSymbolAddress((void**)&qk, g_qk);   cudaGetSymbolAddress((void**)&v, g_v);
    cudaGetSymbolAddress((void**)&xh, g_xh);   cudaGetSymbolAddress((void**)&xl, g_xl);
    cudaGetSymbolAddress((void**)&wqk, g_wqk); cudaGetSymbolAddress((void**)&wv, g_wv);
    cudaGetSymbolAddress((void**)&wo, g_wo);
    cudaGetSymbolAddress((void**)&bqk, g_bqk); cudaGetSymbolAddress((void**)&bv, g_bv);
    cudaGetSymbolAddress((void**)&sa, g_sa);

    cudaFuncSetAttribute(attn_kernel,
                         cudaFuncAttributeMaxDynamicSharedMemorySize, ATTN_SMEM);
    cudaFuncSetAttribute(gemm_tc_kernel,
                         cudaFuncAttributeMaxDynamicSharedMemorySize, GSMEM);

    // 0) operand prep
    {
        const int n4 = MROWS * E_ / 4;
        split_kernel<<<(n4 + 255) / 256, 256>>>(x, xh, xl, n4);
        transpose_permute_kernel<<<dim3(H3 / 32, E_ / 32), dim3(32, 8)>>>(
            W_qkv, wqk, wv, E_, H3);
        transpose_kernel<<<dim3(E_ / 32, E_ / 32), dim3(32, 8)>>>(W_out, wo, E_, E_);
        bias_permute_kernel<<<(H3 + 255) / 256, 256>>>(b_qkv, bqk, bv);
    }

    // 1a) q,k projection (1-pass) -> g_qk [8192, 2048]
    gemm_tc_kernel<<<dim3(2048 / GBN, MROWS / GBM), 256, GSMEM>>>(
        xh, xl, wqk, bqk, nullptr, qk, /*npass=*/1, MROWS, 2048, E_);

    // 1b) v projection (2-pass) -> g_v [8192, 1024]
    gemm_tc_kernel<<<dim3(1024 / GBN, MROWS / GBM), 256, GSMEM>>>(
        xh, xl, wv, bv, nullptr, v, /*npass=*/2, MROWS, 1024, E_);

    // 2) fp16 HMMA causal attention -> single fp16 sa
    attn_kernel<<<dim3(16, B_ * NH), 256, ATTN_SMEM>>>();

    // 3) output projection (1-pass on fp16 sa) -> fp32 out
    gemm_tc_kernel<<<dim3(E_ / GBN, MROWS / GBM), 256, GSMEM>>>(
        sa, sa, wo, b_out, out, nullptr, /*npass=*/1, MROWS, E_, E_);
}